// round 1
// baseline (speedup 1.0000x reference)
#include <cuda_runtime.h>
#include <cuda_bf16.h>
#include <math.h>

// Problem constants
#define Nn   20000
#define Ee   320000
#define Pp   50000
#define Ll   20
#define INF  128
#define HD   64
#define NEe  (Ee + Nn)
#define NC   384   // packed node-GEMM output cols: [anti_pre(64)|M(64)|U(128)|V(128)]

// ---------------- device scratch (no allocation allowed) ----------------
__device__ float g_H[Nn * HD];
__device__ float g_dH[Nn * HD];
__device__ float g_C[(size_t)Nn * NC];       // per-step node GEMM output; reused as T (P x 64) at the end
__device__ float g_B[HD * NC];               // packed weight matrix 64 x 384
__device__ float g_r[(size_t)Pp * 2 * HD];   // r state, P x 128
__device__ float g_a[Nn];                    // H[n] . Wfv[0:64]
__device__ float g_b[Nn];                    // H[n] . Wfv[64:128]
__device__ int   g_deg[Nn];
__device__ float g_dinv[Nn];
__device__ int   g_off[Nn + 1];
__device__ int   g_fill[Nn];
__device__ int   g_csr_row[NEe];
__device__ float g_csr_norm[NEe];

// ---------------- weight packing ----------------
__global__ void k_prepB(const float* __restrict__ Om, const float* __restrict__ Ws,
                        const float* __restrict__ Wfc1) {
    int i = blockIdx.x * blockDim.x + threadIdx.x;
    if (i >= HD * NC) return;
    int k = i / NC, j = i % NC;
    float v;
    if (j < 64)       v = Om[k * 64 + j] - Om[j * 64 + k];              // Omega - Omega^T
    else if (j < 128) { int jj = j - 64; v = 0.5f * (Ws[k * 64 + jj] + Ws[jj * 64 + k]); }
    else if (j < 256) v = Wfc1[k * 128 + (j - 128)];                    // top half rows
    else              v = Wfc1[(64 + k) * 128 + (j - 256)];            // bottom half rows
    g_B[k * NC + j] = v;
}

// ---------------- graph preprocessing ----------------
__global__ void k_init() {
    int i = blockIdx.x * blockDim.x + threadIdx.x;
    if (i < Nn) { g_deg[i] = 1; g_fill[i] = 0; }   // self-loop counts as 1
}

__global__ void k_deg(const int* __restrict__ ei) {
    int e = blockIdx.x * blockDim.x + threadIdx.x;
    if (e < Ee) atomicAdd(&g_deg[ei[Ee + e]], 1);
}

__global__ void k_dinv() {
    int n = blockIdx.x * blockDim.x + threadIdx.x;
    if (n < Nn) g_dinv[n] = rsqrtf((float)g_deg[n]);
}

__global__ void k_scan() {  // 1 block, 1024 threads: exclusive scan of deg -> off
    __shared__ int sh[1024];
    __shared__ int carry_s;
    int t = threadIdx.x;
    if (t == 0) carry_s = 0;
    __syncthreads();
    for (int base = 0; base < Nn; base += 1024) {
        int v = (base + t < Nn) ? g_deg[base + t] : 0;
        int x = v;
        for (int off = 1; off < 1024; off <<= 1) {
            sh[t] = x; __syncthreads();
            if (t >= off) x += sh[t - off];
            __syncthreads();
        }
        int carry = carry_s;
        if (base + t < Nn) g_off[base + t] = carry + x - v;
        __syncthreads();
        if (t == 1023) carry_s = carry + x;
        __syncthreads();
    }
    if (t == 0) g_off[Nn] = carry_s;
}

__global__ void k_fill(const int* __restrict__ ei) {
    int e = blockIdx.x * blockDim.x + threadIdx.x;
    if (e >= NEe) return;
    int r_, c_;
    if (e < Ee) { r_ = ei[e]; c_ = ei[Ee + e]; }
    else        { r_ = c_ = e - Ee; }
    int pos = g_off[c_] + atomicAdd(&g_fill[c_], 1);
    g_csr_row[pos]  = r_;
    g_csr_norm[pos] = g_dinv[r_] * g_dinv[c_];
}

// ---------------- SGEMM: C = act(A[MxK] @ B[KxNCb]) row-major ----------------
#define BMt 64
#define BNt 64
#define BKt 16
#define TMt 4
#define TNt 8
// 128 threads: 16 row-groups x 8 col-groups
__global__ __launch_bounds__(128) void sgemm(const float* __restrict__ A,
                                             const float* __restrict__ B,
                                             float* __restrict__ Cc,
                                             int M, int K, int NCb, int act) {
    __shared__ float As[BKt][BMt];
    __shared__ float Bs[BKt][BNt];
    int block_row = blockIdx.y * BMt;
    int block_col = blockIdx.x * BNt;
    int tid = threadIdx.x;
    int ty = tid >> 3;          // 0..15
    int tx = tid & 7;           // 0..7
    int row0 = ty * TMt;
    int col0 = tx * TNt;
    float acc[TMt][TNt];
#pragma unroll
    for (int i = 0; i < TMt; i++)
#pragma unroll
        for (int j = 0; j < TNt; j++) acc[i][j] = 0.f;

    for (int k0 = 0; k0 < K; k0 += BKt) {
        // load A tile transposed: 64 rows x 16 k  (256 float4 / 128 thr = 2 each)
#pragma unroll
        for (int t = 0; t < 2; t++) {
            int idx = tid * 2 + t;
            int r = idx >> 2;
            int c4 = (idx & 3) * 4;
            int gr = block_row + r;
            float4 v = make_float4(0.f, 0.f, 0.f, 0.f);
            if (gr < M) v = *reinterpret_cast<const float4*>(&A[(size_t)gr * K + k0 + c4]);
            As[c4 + 0][r] = v.x; As[c4 + 1][r] = v.y;
            As[c4 + 2][r] = v.z; As[c4 + 3][r] = v.w;
        }
        // load B tile: 16 k x 64 n
#pragma unroll
        for (int t = 0; t < 2; t++) {
            int idx = tid * 2 + t;
            int k = idx >> 4;
            int n4 = (idx & 15) * 4;
            float4 v = *reinterpret_cast<const float4*>(&B[(size_t)(k0 + k) * NCb + block_col + n4]);
            *reinterpret_cast<float4*>(&Bs[k][n4]) = v;
        }
        __syncthreads();
#pragma unroll
        for (int k = 0; k < BKt; k++) {
            float4 a4  = *reinterpret_cast<const float4*>(&As[k][row0]);
            float4 b4a = *reinterpret_cast<const float4*>(&Bs[k][col0]);
            float4 b4b = *reinterpret_cast<const float4*>(&Bs[k][col0 + 4]);
            float av[TMt] = {a4.x, a4.y, a4.z, a4.w};
            float bv[TNt] = {b4a.x, b4a.y, b4a.z, b4a.w, b4b.x, b4b.y, b4b.z, b4b.w};
#pragma unroll
            for (int i = 0; i < TMt; i++)
#pragma unroll
                for (int j = 0; j < TNt; j++)
                    acc[i][j] += av[i] * bv[j];
        }
        __syncthreads();
    }
#pragma unroll
    for (int i = 0; i < TMt; i++) {
        int gr = block_row + row0 + i;
        if (gr < M) {
#pragma unroll
            for (int j = 0; j < TNt; j++) {
                float v = acc[i][j];
                if (act) v = fmaxf(v, 0.f);
                Cc[(size_t)gr * NCb + block_col + col0 + j] = v;
            }
        }
    }
}

// ---------------- init r and ts ----------------
__global__ void k_r0(const int* __restrict__ pairs) {
    int idx = blockIdx.x * blockDim.x + threadIdx.x;
    if (idx >= Pp * 128) return;
    int p = idx >> 7, j = idx & 127;
    int s = pairs[2 * p], d = pairs[2 * p + 1];
    g_r[idx] = (j < 64) ? g_H[s * HD + j] : g_H[d * HD + j - 64];
}

__global__ void k_ts0(float* __restrict__ out) {
    int idx = blockIdx.x * blockDim.x + threadIdx.x;
    if (idx < Pp) out[Pp + idx] = 0.f;
}

// ---------------- per-node: sym gather, dH, nu partials ----------------
__global__ __launch_bounds__(256) void k_node(const float* __restrict__ Wfv) {
    int warp = (blockIdx.x * blockDim.x + threadIdx.x) >> 5;
    int lane = threadIdx.x & 31;
    if (warp >= Nn) return;
    int n = warp;
    int beg = g_off[n], end = g_off[n + 1];
    float s0 = 0.f, s1 = 0.f;
    for (int i = beg; i < end; i++) {
        int rs = g_csr_row[i];
        float w = g_csr_norm[i];
        const float* Mrow = &g_C[(size_t)rs * NC + 64];
        s0 += Mrow[lane] * w;
        s1 += Mrow[lane + 32] * w;
    }
    float a0 = g_C[(size_t)n * NC + lane];
    float a1 = g_C[(size_t)n * NC + 32 + lane];
    float dh0 = fmaxf(tanhf(s0 - fmaxf(a0, 0.f)), 0.f);
    float dh1 = fmaxf(tanhf(s1 - fmaxf(a1, 0.f)), 0.f);
    g_dH[n * HD + lane]      = dh0;
    g_dH[n * HD + lane + 32] = dh1;
    // nu partials: a[n]=H.Wfv_top, b[n]=H.Wfv_bot
    float h0 = g_H[n * HD + lane], h1 = g_H[n * HD + lane + 32];
    float pa = h0 * Wfv[lane]      + h1 * Wfv[lane + 32];
    float pb = h0 * Wfv[64 + lane] + h1 * Wfv[96 + lane];
#pragma unroll
    for (int o = 16; o > 0; o >>= 1) {
        pa += __shfl_xor_sync(0xffffffffu, pa, o);
        pb += __shfl_xor_sync(0xffffffffu, pb, o);
    }
    if (lane == 0) { g_a[n] = pa; g_b[n] = pb; }
}

// ---------------- per-pair: logits, tau, r/ts update ----------------
__global__ __launch_bounds__(256) void k_pair(const int* __restrict__ pairs,
                                              const float* __restrict__ gum,
                                              const float* __restrict__ Wfc2,
                                              float* __restrict__ out, int l) {
    int warp = (blockIdx.x * blockDim.x + threadIdx.x) >> 5;
    int lane = threadIdx.x & 31;
    if (warp >= Pp) return;
    int p = warp;
    int s = pairs[2 * p], d = pairs[2 * p + 1];
    const float* Us = &g_C[(size_t)s * NC + 128];
    const float* Vd = &g_C[(size_t)d * NC + 256];
    float l0 = 0.f, l1 = 0.f;
#pragma unroll
    for (int i = 0; i < 4; i++) {
        int j = lane + 32 * i;
        float hv = fmaxf(Us[j] + Vd[j], 0.f);
        l0 += hv * Wfc2[2 * j];
        l1 += hv * Wfc2[2 * j + 1];
    }
#pragma unroll
    for (int o = 16; o > 0; o >>= 1) {
        l0 += __shfl_xor_sync(0xffffffffu, l0, o);
        l1 += __shfl_xor_sync(0xffffffffu, l1, o);
    }
    float z  = g_a[s] + g_b[d];
    float nu = fmaxf(z, 0.f) + log1pf(expf(-fabsf(z))) + 1.0f;   // softplus + NU0
    float g0 = gum[((size_t)l * Pp + p) * 2];
    float g1 = gum[((size_t)l * Pp + p) * 2 + 1];
    float diff = ((l1 + g1) - (l0 + g0)) / nu;
    float tau  = 1.f / (1.f + expf(diff));     // softmax component 0
    const float* dHs = &g_dH[s * HD];
    const float* dHd = &g_dH[d * HD];
    float* rp = &g_r[(size_t)p * 2 * HD];
#pragma unroll
    for (int i = 0; i < 4; i++) {
        int j = lane + 32 * i;
        float dr = (j < 64) ? dHs[j] : dHd[j - 64];
        rp[j] += tau * dr;
    }
    if (lane == 0) out[Pp + p] += tau;
}

__global__ void k_updH() {
    int i = blockIdx.x * blockDim.x + threadIdx.x;
    if (i < Nn * HD) g_H[i] += g_dH[i];
}

// ---------------- final scores: out[p] = sum_j relu(T[p][j]) * Wp2[j] ----------------
__global__ __launch_bounds__(256) void k_score(const float* __restrict__ Wp2,
                                               float* __restrict__ out) {
    int warp = (blockIdx.x * blockDim.x + threadIdx.x) >> 5;
    int lane = threadIdx.x & 31;
    if (warp >= Pp) return;
    int p = warp;
    // T stored in g_C, already relu'ed by sgemm epilogue (act=1)
    float t0 = g_C[(size_t)p * 64 + 2 * lane];
    float t1 = g_C[(size_t)p * 64 + 2 * lane + 1];
    float acc = t0 * Wp2[2 * lane] + t1 * Wp2[2 * lane + 1];
#pragma unroll
    for (int o = 16; o > 0; o >>= 1) acc += __shfl_xor_sync(0xffffffffu, acc, o);
    if (lane == 0) out[p] = acc;
}

// ---------------- host ----------------
extern "C" void kernel_launch(void* const* d_in, const int* in_sizes, int n_in,
                              void* d_out, int out_size) {
    const float* x    = (const float*)d_in[0];
    const int*   ei   = (const int*)d_in[1];
    const int*   pairs= (const int*)d_in[2];
    const float* gum  = (const float*)d_in[3];
    const float* Wenc = (const float*)d_in[4];
    const float* Om   = (const float*)d_in[5];
    const float* Wsr  = (const float*)d_in[6];
    const float* Wfc1 = (const float*)d_in[7];
    const float* Wfc2 = (const float*)d_in[8];
    const float* Wfv  = (const float*)d_in[9];
    const float* Wp1  = (const float*)d_in[10];
    const float* Wp2  = (const float*)d_in[11];
    float* out = (float*)d_out;

    void *pH, *pB, *pC, *pR;
    cudaGetSymbolAddress(&pH, g_H);
    cudaGetSymbolAddress(&pB, g_B);
    cudaGetSymbolAddress(&pC, g_C);
    cudaGetSymbolAddress(&pR, g_r);
    float* H_ = (float*)pH;
    float* B_ = (float*)pB;
    float* C_ = (float*)pC;
    float* R_ = (float*)pR;

    // weights + graph prep
    k_prepB<<<(HD * NC + 255) / 256, 256>>>(Om, Wsr, Wfc1);
    k_init<<<(Nn + 255) / 256, 256>>>();
    k_deg<<<(Ee + 255) / 256, 256>>>(ei);
    k_dinv<<<(Nn + 255) / 256, 256>>>();
    k_scan<<<1, 1024>>>();
    k_fill<<<(NEe + 255) / 256, 256>>>(ei);

    // H0 = relu(x @ W_enc)
    sgemm<<<dim3(1, (Nn + BMt - 1) / BMt), 128>>>(x, Wenc, H_, Nn, INF, HD, 1);
    // r0 = [H0[src], H0[dst]], ts = 0
    k_r0<<<(Pp * 128 + 255) / 256, 256>>>(pairs);
    k_ts0<<<(Pp + 255) / 256, 256>>>(out);

    for (int l = 0; l < Ll; l++) {
        // C = H @ [Omega_as | W_s | Wfc1_top | Wfc1_bot]
        sgemm<<<dim3(NC / BNt, (Nn + BMt - 1) / BMt), 128>>>(H_, B_, C_, Nn, HD, NC, 0);
        k_node<<<(Nn * 32) / 256, 256>>>(Wfv);
        k_pair<<<(Pp * 32) / 256, 256>>>(pairs, gum, Wfc2, out, l);
        k_updH<<<(Nn * HD + 255) / 256, 256>>>();
    }

    // T = relu(r @ W_p1) into g_C, then scores = T @ W_p2
    sgemm<<<dim3(1, (Pp + BMt - 1) / BMt), 128>>>(R_, Wp1, C_, Pp, 2 * HD, HD, 1);
    k_score<<<(Pp * 32) / 256, 256>>>(Wp2, out);
}

// round 3
// speedup vs baseline: 1.5191x; 1.5191x over previous
#include <cuda_runtime.h>
#include <cuda_bf16.h>
#include <math.h>
#include <stdint.h>

// Problem constants
#define Nn   20000
#define Ee   320000
#define Pp   50000
#define Ll   20
#define INF  128
#define HD   64
#define NEe  (Ee + Nn)
#define NC   384   // packed node-GEMM output cols: [anti_pre(64)|M(64)|U(128)|V(128)]

// ---------------- device scratch (no allocation allowed) ----------------
__device__ float g_H[Nn * HD];
__device__ float g_dH[Nn * HD];
__device__ float g_C[(size_t)Nn * NC];       // per-step node GEMM output; reused as T (P x 64) at the end
__device__ __nv_bfloat16 g_Hhi[Nn * HD];
__device__ __nv_bfloat16 g_Hlo[Nn * HD];
__device__ __nv_bfloat16 g_Bhi[NC * HD];     // packed weights, [n][k] layout (384 x 64)
__device__ __nv_bfloat16 g_Blo[NC * HD];
__device__ float g_r[(size_t)Pp * 2 * HD];   // r state, P x 128
__device__ float g_a[Nn];                    // H[n] . Wfv[0:64]
__device__ float g_b[Nn];                    // H[n] . Wfv[64:128]
__device__ int   g_deg[Nn];
__device__ float g_dinv[Nn];
__device__ int   g_off[Nn + 1];
__device__ int   g_fill[Nn];
__device__ int   g_csr_row[NEe];
__device__ float g_csr_norm[NEe];

// ---------------- HMMA step GEMM: C[Nn x 384] = H @ Bpacked ----------------
// bf16x3 split: C = Ahi*Bhi + Ahi*Blo + Alo*Bhi  (fp32 accumulate)
// mma.sync.aligned.m16n8k16.row.col.f32.bf16.bf16.f32
// A (row-major M x K), B stored [n][k] == col-major K x N. K = 64.
// CTA tile: 128 rows x 192 cols, 512 threads (16 warps, 4m x 4n), warp tile 32 x 48.
// SMEM: padded row stride 72 bf16 (144 B) -> fragment LDS bank = (4g+t), conflict-free.
#define S_AHI 0
#define S_ALO 18432                 // 128*144
#define S_BHI 36864
#define S_BLO (36864 + 27648)       // 192*144
#define S_TOT (S_BLO + 27648)       // 92160

__device__ __forceinline__ void hmma(float* d, uint32_t a0, uint32_t a1,
                                     uint32_t a2, uint32_t a3,
                                     uint32_t b0, uint32_t b1) {
    asm volatile(
        "mma.sync.aligned.m16n8k16.row.col.f32.bf16.bf16.f32 "
        "{%0,%1,%2,%3}, {%4,%5,%6,%7}, {%8,%9}, {%0,%1,%2,%3};\n"
        : "+f"(d[0]), "+f"(d[1]), "+f"(d[2]), "+f"(d[3])
        : "r"(a0), "r"(a1), "r"(a2), "r"(a3), "r"(b0), "r"(b1));
}

__global__ __launch_bounds__(512, 1) void mma_step(
    const __nv_bfloat16* __restrict__ Ahi, const __nv_bfloat16* __restrict__ Alo) {
    extern __shared__ char sm[];
    const int tid = threadIdx.x;
    const int brow = blockIdx.x * 128;
    const int bcol = blockIdx.y * 192;

    // Fill A tiles (hi/lo): 128 rows x 64 k -> 1024 uint4 per buffer, 2/thread
#pragma unroll
    for (int i = 0; i < 2; i++) {
        int idx = tid * 2 + i;
        int r = idx >> 3, c = idx & 7;
        int gr = brow + r;
        uint4 vh = make_uint4(0, 0, 0, 0), vl = make_uint4(0, 0, 0, 0);
        if (gr < Nn) {
            vh = *reinterpret_cast<const uint4*>(&Ahi[(size_t)gr * HD + c * 8]);
            vl = *reinterpret_cast<const uint4*>(&Alo[(size_t)gr * HD + c * 8]);
        }
        *reinterpret_cast<uint4*>(sm + S_AHI + r * 144 + c * 16) = vh;
        *reinterpret_cast<uint4*>(sm + S_ALO + r * 144 + c * 16) = vl;
    }
    // Fill B tiles (hi/lo): 192 rows x 64 k -> 1536 uint4 per buffer, 3/thread
#pragma unroll
    for (int i = 0; i < 3; i++) {
        int idx = tid * 3 + i;
        int r = idx >> 3, c = idx & 7;
        *reinterpret_cast<uint4*>(sm + S_BHI + r * 144 + c * 16) =
            *reinterpret_cast<const uint4*>(&g_Bhi[(size_t)(bcol + r) * HD + c * 8]);
        *reinterpret_cast<uint4*>(sm + S_BLO + r * 144 + c * 16) =
            *reinterpret_cast<const uint4*>(&g_Blo[(size_t)(bcol + r) * HD + c * 8]);
    }
    __syncthreads();

    const int wid = tid >> 5, lane = tid & 31;
    const int wm = wid >> 2, wn = wid & 3;
    const int g = lane >> 2, t = lane & 3;

    float acc[2][6][4];
#pragma unroll
    for (int mt = 0; mt < 2; mt++)
#pragma unroll
        for (int nt = 0; nt < 6; nt++)
#pragma unroll
            for (int q = 0; q < 4; q++) acc[mt][nt][q] = 0.f;

#pragma unroll
    for (int ab = 0; ab < 3; ab++) {
        const char* Ab = sm + ((ab == 2) ? S_ALO : S_AHI);
        const char* Bb = sm + ((ab == 1) ? S_BLO : S_BHI);
#pragma unroll
        for (int kc = 0; kc < 4; kc++) {
            int kb = kc * 32 + t * 4;
            uint32_t bf[6][2];
#pragma unroll
            for (int nt = 0; nt < 6; nt++) {
                int nr = wn * 48 + nt * 8 + g;
                bf[nt][0] = *reinterpret_cast<const uint32_t*>(Bb + nr * 144 + kb);
                bf[nt][1] = *reinterpret_cast<const uint32_t*>(Bb + nr * 144 + kb + 16);
            }
#pragma unroll
            for (int mt = 0; mt < 2; mt++) {
                int r0 = wm * 32 + mt * 16 + g;
                uint32_t a0 = *reinterpret_cast<const uint32_t*>(Ab + r0 * 144 + kb);
                uint32_t a1 = *reinterpret_cast<const uint32_t*>(Ab + (r0 + 8) * 144 + kb);
                uint32_t a2 = *reinterpret_cast<const uint32_t*>(Ab + r0 * 144 + kb + 16);
                uint32_t a3 = *reinterpret_cast<const uint32_t*>(Ab + (r0 + 8) * 144 + kb + 16);
#pragma unroll
                for (int nt = 0; nt < 6; nt++)
                    hmma(acc[mt][nt], a0, a1, a2, a3, bf[nt][0], bf[nt][1]);
            }
        }
    }

    // Epilogue: c0/c1 -> (row, 2t..2t+1), c2/c3 -> (row+8, 2t..2t+1)
#pragma unroll
    for (int mt = 0; mt < 2; mt++) {
#pragma unroll
        for (int nt = 0; nt < 6; nt++) {
            int row = brow + wm * 32 + mt * 16 + g;
            int col = bcol + wn * 48 + nt * 8 + 2 * t;
            if (row < Nn) {
                float2 v = make_float2(acc[mt][nt][0], acc[mt][nt][1]);
                *reinterpret_cast<float2*>(&g_C[(size_t)row * NC + col]) = v;
            }
            if (row + 8 < Nn) {
                float2 v = make_float2(acc[mt][nt][2], acc[mt][nt][3]);
                *reinterpret_cast<float2*>(&g_C[(size_t)(row + 8) * NC + col]) = v;
            }
        }
    }
}

// ---------------- weight packing: Bhi/Blo in [n][k] (col-major B for HMMA) ----------------
__global__ void k_prepB(const float* __restrict__ Om, const float* __restrict__ Ws,
                        const float* __restrict__ Wfc1) {
    int i = blockIdx.x * blockDim.x + threadIdx.x;
    if (i >= HD * NC) return;
    int k = i / NC, j = i % NC;
    float v;
    if (j < 64)       v = Om[k * 64 + j] - Om[j * 64 + k];              // Omega - Omega^T
    else if (j < 128) { int jj = j - 64; v = 0.5f * (Ws[k * 64 + jj] + Ws[jj * 64 + k]); }
    else if (j < 256) v = Wfc1[k * 128 + (j - 128)];                    // top half rows
    else              v = Wfc1[(64 + k) * 128 + (j - 256)];            // bottom half rows
    __nv_bfloat16 hi = __float2bfloat16(v);
    __nv_bfloat16 lo = __float2bfloat16(v - __bfloat162float(hi));
    g_Bhi[(size_t)j * HD + k] = hi;
    g_Blo[(size_t)j * HD + k] = lo;
}

// ---------------- graph preprocessing ----------------
__global__ void k_init() {
    int i = blockIdx.x * blockDim.x + threadIdx.x;
    if (i < Nn) { g_deg[i] = 1; g_fill[i] = 0; }   // self-loop counts as 1
}

__global__ void k_deg(const int* __restrict__ ei) {
    int e = blockIdx.x * blockDim.x + threadIdx.x;
    if (e < Ee) atomicAdd(&g_deg[ei[Ee + e]], 1);
}

__global__ void k_dinv() {
    int n = blockIdx.x * blockDim.x + threadIdx.x;
    if (n < Nn) g_dinv[n] = rsqrtf((float)g_deg[n]);
}

__global__ void k_scan() {  // 1 block, 1024 threads: exclusive scan of deg -> off
    __shared__ int sh[1024];
    __shared__ int carry_s;
    int t = threadIdx.x;
    if (t == 0) carry_s = 0;
    __syncthreads();
    for (int base = 0; base < Nn; base += 1024) {
        int v = (base + t < Nn) ? g_deg[base + t] : 0;
        int x = v;
        for (int off = 1; off < 1024; off <<= 1) {
            sh[t] = x; __syncthreads();
            if (t >= off) x += sh[t - off];
            __syncthreads();
        }
        int carry = carry_s;
        if (base + t < Nn) g_off[base + t] = carry + x - v;
        __syncthreads();
        if (t == 1023) carry_s = carry + x;
        __syncthreads();
    }
    if (t == 0) g_off[Nn] = carry_s;
}

__global__ void k_fill(const int* __restrict__ ei) {
    int e = blockIdx.x * blockDim.x + threadIdx.x;
    if (e >= NEe) return;
    int r_, c_;
    if (e < Ee) { r_ = ei[e]; c_ = ei[Ee + e]; }
    else        { r_ = c_ = e - Ee; }
    int pos = g_off[c_] + atomicAdd(&g_fill[c_], 1);
    g_csr_row[pos]  = r_;
    g_csr_norm[pos] = g_dinv[r_] * g_dinv[c_];
}

// ---------------- scalar SGEMM (used for H0 and final projection only) ----------------
#define BMt 64
#define BNt 64
#define BKt 16
#define TMt 4
#define TNt 8
__global__ __launch_bounds__(128) void sgemm(const float* __restrict__ A,
                                             const float* __restrict__ B,
                                             float* __restrict__ Cc,
                                             int M, int K, int NCb, int act) {
    __shared__ float As[BKt][BMt];
    __shared__ float Bs[BKt][BNt];
    int block_row = blockIdx.y * BMt;
    int block_col = blockIdx.x * BNt;
    int tid = threadIdx.x;
    int ty = tid >> 3;
    int tx = tid & 7;
    int row0 = ty * TMt;
    int col0 = tx * TNt;
    float acc[TMt][TNt];
#pragma unroll
    for (int i = 0; i < TMt; i++)
#pragma unroll
        for (int j = 0; j < TNt; j++) acc[i][j] = 0.f;

    for (int k0 = 0; k0 < K; k0 += BKt) {
#pragma unroll
        for (int t = 0; t < 2; t++) {
            int idx = tid * 2 + t;
            int r = idx >> 2;
            int c4 = (idx & 3) * 4;
            int gr = block_row + r;
            float4 v = make_float4(0.f, 0.f, 0.f, 0.f);
            if (gr < M) v = *reinterpret_cast<const float4*>(&A[(size_t)gr * K + k0 + c4]);
            As[c4 + 0][r] = v.x; As[c4 + 1][r] = v.y;
            As[c4 + 2][r] = v.z; As[c4 + 3][r] = v.w;
        }
#pragma unroll
        for (int t = 0; t < 2; t++) {
            int idx = tid * 2 + t;
            int k = idx >> 4;
            int n4 = (idx & 15) * 4;
            float4 v = *reinterpret_cast<const float4*>(&B[(size_t)(k0 + k) * NCb + block_col + n4]);
            *reinterpret_cast<float4*>(&Bs[k][n4]) = v;
        }
        __syncthreads();
#pragma unroll
        for (int k = 0; k < BKt; k++) {
            float4 a4  = *reinterpret_cast<const float4*>(&As[k][row0]);
            float4 b4a = *reinterpret_cast<const float4*>(&Bs[k][col0]);
            float4 b4b = *reinterpret_cast<const float4*>(&Bs[k][col0 + 4]);
            float av[TMt] = {a4.x, a4.y, a4.z, a4.w};
            float bv[TNt] = {b4a.x, b4a.y, b4a.z, b4a.w, b4b.x, b4b.y, b4b.z, b4b.w};
#pragma unroll
            for (int i = 0; i < TMt; i++)
#pragma unroll
                for (int j = 0; j < TNt; j++)
                    acc[i][j] += av[i] * bv[j];
        }
        __syncthreads();
    }
#pragma unroll
    for (int i = 0; i < TMt; i++) {
        int gr = block_row + row0 + i;
        if (gr < M) {
#pragma unroll
            for (int j = 0; j < TNt; j++) {
                float v = acc[i][j];
                if (act) v = fmaxf(v, 0.f);
                Cc[(size_t)gr * NCb + block_col + col0 + j] = v;
            }
        }
    }
}

// ---------------- H -> bf16 hi/lo conversion (initial) ----------------
__global__ void k_h2b() {
    int i = blockIdx.x * blockDim.x + threadIdx.x;
    if (i >= Nn * HD) return;
    float x = g_H[i];
    __nv_bfloat16 hi = __float2bfloat16(x);
    g_Hhi[i] = hi;
    g_Hlo[i] = __float2bfloat16(x - __bfloat162float(hi));
}

// ---------------- init r and ts ----------------
__global__ void k_r0(const int* __restrict__ pairs) {
    int idx = blockIdx.x * blockDim.x + threadIdx.x;
    if (idx >= Pp * 128) return;
    int p = idx >> 7, j = idx & 127;
    int s = pairs[2 * p], d = pairs[2 * p + 1];
    g_r[idx] = (j < 64) ? g_H[s * HD + j] : g_H[d * HD + j - 64];
}

__global__ void k_ts0(float* __restrict__ out) {
    int idx = blockIdx.x * blockDim.x + threadIdx.x;
    if (idx < Pp) out[Pp + idx] = 0.f;
}

// ---------------- per-node: sym gather, dH, nu partials, H update, bf16 emit ----------------
__global__ __launch_bounds__(256) void k_node(const float* __restrict__ Wfv) {
    int warp = (blockIdx.x * blockDim.x + threadIdx.x) >> 5;
    int lane = threadIdx.x & 31;
    if (warp >= Nn) return;
    int n = warp;
    int beg = g_off[n], end = g_off[n + 1];
    float s0 = 0.f, s1 = 0.f;
    for (int i = beg; i < end; i++) {
        int rs = g_csr_row[i];
        float w = g_csr_norm[i];
        const float* Mrow = &g_C[(size_t)rs * NC + 64];
        s0 += Mrow[lane] * w;
        s1 += Mrow[lane + 32] * w;
    }
    float a0 = g_C[(size_t)n * NC + lane];
    float a1 = g_C[(size_t)n * NC + 32 + lane];
    float dh0 = fmaxf(tanhf(s0 - fmaxf(a0, 0.f)), 0.f);
    float dh1 = fmaxf(tanhf(s1 - fmaxf(a1, 0.f)), 0.f);
    g_dH[n * HD + lane]      = dh0;
    g_dH[n * HD + lane + 32] = dh1;
    // nu partials from OLD H
    float h0 = g_H[n * HD + lane], h1 = g_H[n * HD + lane + 32];
    float pa = h0 * Wfv[lane]      + h1 * Wfv[lane + 32];
    float pb = h0 * Wfv[64 + lane] + h1 * Wfv[96 + lane];
#pragma unroll
    for (int o = 16; o > 0; o >>= 1) {
        pa += __shfl_xor_sync(0xffffffffu, pa, o);
        pb += __shfl_xor_sync(0xffffffffu, pb, o);
    }
    if (lane == 0) { g_a[n] = pa; g_b[n] = pb; }
    // H update in place + bf16 hi/lo emit for next step's MMA
    float hn0 = h0 + dh0, hn1 = h1 + dh1;
    g_H[n * HD + lane]      = hn0;
    g_H[n * HD + lane + 32] = hn1;
    __nv_bfloat16 hi0 = __float2bfloat16(hn0);
    __nv_bfloat16 hi1 = __float2bfloat16(hn1);
    g_Hhi[n * HD + lane]      = hi0;
    g_Hhi[n * HD + lane + 32] = hi1;
    g_Hlo[n * HD + lane]      = __float2bfloat16(hn0 - __bfloat162float(hi0));
    g_Hlo[n * HD + lane + 32] = __float2bfloat16(hn1 - __bfloat162float(hi1));
}

// ---------------- per-pair: logits, tau, r/ts update ----------------
__global__ __launch_bounds__(256) void k_pair(const int* __restrict__ pairs,
                                              const float* __restrict__ gum,
                                              const float* __restrict__ Wfc2,
                                              float* __restrict__ out, int l) {
    int warp = (blockIdx.x * blockDim.x + threadIdx.x) >> 5;
    int lane = threadIdx.x & 31;
    if (warp >= Pp) return;
    int p = warp;
    int s = pairs[2 * p], d = pairs[2 * p + 1];
    const float* Us = &g_C[(size_t)s * NC + 128];
    const float* Vd = &g_C[(size_t)d * NC + 256];
    float l0 = 0.f, l1 = 0.f;
#pragma unroll
    for (int i = 0; i < 4; i++) {
        int j = lane + 32 * i;
        float hv = fmaxf(Us[j] + Vd[j], 0.f);
        l0 += hv * Wfc2[2 * j];
        l1 += hv * Wfc2[2 * j + 1];
    }
#pragma unroll
    for (int o = 16; o > 0; o >>= 1) {
        l0 += __shfl_xor_sync(0xffffffffu, l0, o);
        l1 += __shfl_xor_sync(0xffffffffu, l1, o);
    }
    float z  = g_a[s] + g_b[d];
    float nu = fmaxf(z, 0.f) + log1pf(expf(-fabsf(z))) + 1.0f;   // softplus + NU0
    float g0 = gum[((size_t)l * Pp + p) * 2];
    float g1 = gum[((size_t)l * Pp + p) * 2 + 1];
    float diff = ((l1 + g1) - (l0 + g0)) / nu;
    float tau  = 1.f / (1.f + expf(diff));     // softmax component 0
    const float* dHs = &g_dH[s * HD];
    const float* dHd = &g_dH[d * HD];
    float* rp = &g_r[(size_t)p * 2 * HD];
#pragma unroll
    for (int i = 0; i < 4; i++) {
        int j = lane + 32 * i;
        float dr = (j < 64) ? dHs[j] : dHd[j - 64];
        rp[j] += tau * dr;
    }
    if (lane == 0) out[Pp + p] += tau;
}

// ---------------- final scores ----------------
__global__ __launch_bounds__(256) void k_score(const float* __restrict__ Wp2,
                                               float* __restrict__ out) {
    int warp = (blockIdx.x * blockDim.x + threadIdx.x) >> 5;
    int lane = threadIdx.x & 31;
    if (warp >= Pp) return;
    int p = warp;
    float t0 = g_C[(size_t)p * 64 + 2 * lane];
    float t1 = g_C[(size_t)p * 64 + 2 * lane + 1];
    float acc = t0 * Wp2[2 * lane] + t1 * Wp2[2 * lane + 1];
#pragma unroll
    for (int o = 16; o > 0; o >>= 1) acc += __shfl_xor_sync(0xffffffffu, acc, o);
    if (lane == 0) out[p] = acc;
}

// ---------------- host ----------------
extern "C" void kernel_launch(void* const* d_in, const int* in_sizes, int n_in,
                              void* d_out, int out_size) {
    const float* x    = (const float*)d_in[0];
    const int*   ei   = (const int*)d_in[1];
    const int*   pairs= (const int*)d_in[2];
    const float* gum  = (const float*)d_in[3];
    const float* Wenc = (const float*)d_in[4];
    const float* Om   = (const float*)d_in[5];
    const float* Wsr  = (const float*)d_in[6];
    const float* Wfc1 = (const float*)d_in[7];
    const float* Wfc2 = (const float*)d_in[8];
    const float* Wfv  = (const float*)d_in[9];
    const float* Wp1  = (const float*)d_in[10];
    const float* Wp2  = (const float*)d_in[11];
    float* out = (float*)d_out;

    void *pH, *pC, *pR, *pHhi, *pHlo;
    cudaGetSymbolAddress(&pH, g_H);
    cudaGetSymbolAddress(&pC, g_C);
    cudaGetSymbolAddress(&pR, g_r);
    cudaGetSymbolAddress(&pHhi, g_Hhi);
    cudaGetSymbolAddress(&pHlo, g_Hlo);
    float* H_ = (float*)pH;
    float* C_ = (float*)pC;
    float* R_ = (float*)pR;
    const __nv_bfloat16* Hhi_ = (const __nv_bfloat16*)pHhi;
    const __nv_bfloat16* Hlo_ = (const __nv_bfloat16*)pHlo;

    cudaFuncSetAttribute(mma_step, cudaFuncAttributeMaxDynamicSharedMemorySize, S_TOT);

    // weights + graph prep
    k_prepB<<<(HD * NC + 255) / 256, 256>>>(Om, Wsr, Wfc1);
    k_init<<<(Nn + 255) / 256, 256>>>();
    k_deg<<<(Ee + 255) / 256, 256>>>(ei);
    k_dinv<<<(Nn + 255) / 256, 256>>>();
    k_scan<<<1, 1024>>>();
    k_fill<<<(NEe + 255) / 256, 256>>>(ei);

    // H0 = relu(x @ W_enc)
    sgemm<<<dim3(1, (Nn + BMt - 1) / BMt), 128>>>(x, Wenc, H_, Nn, INF, HD, 1);
    k_h2b<<<(Nn * HD + 255) / 256, 256>>>();
    // r0 = [H0[src], H0[dst]], ts = 0
    k_r0<<<(Pp * 128 + 255) / 256, 256>>>(pairs);
    k_ts0<<<(Pp + 255) / 256, 256>>>(out);

    dim3 grid_mma((Nn + 127) / 128, 2);
    for (int l = 0; l < Ll; l++) {
        mma_step<<<grid_mma, 512, S_TOT>>>(Hhi_, Hlo_);
        k_node<<<(Nn * 32) / 256, 256>>>(Wfv);
        k_pair<<<(Pp * 32) / 256, 256>>>(pairs, gum, Wfc2, out, l);
    }

    // T = relu(r @ W_p1) into g_C, then scores = T @ W_p2
    sgemm<<<dim3(1, (Pp + BMt - 1) / BMt), 128>>>(R_, Wp1, C_, Pp, 2 * HD, HD, 1);
    k_score<<<(Pp * 32) / 256, 256>>>(Wp2, out);
}

// round 4
// speedup vs baseline: 1.7429x; 1.1473x over previous
#include <cuda_runtime.h>
#include <cuda_bf16.h>
#include <math.h>
#include <stdint.h>

// Problem constants
#define Nn   20000
#define Ee   320000
#define Pp   50000
#define Ll   20
#define INF  128
#define HD   64
#define NEe  (Ee + Nn)
#define NC   384   // packed node-GEMM output cols: [anti_pre(64)|M(64)|U(128)|V(128)]

// ---------------- device scratch (no allocation allowed) ----------------
__device__ float g_H[Nn * HD];
__device__ float g_H0[Nn * HD];
__device__ float g_dHall[(size_t)Ll * Nn * HD];   // all step dH slabs (102.4 MB)
__device__ float g_tau[(size_t)Ll * Pp];          // tau per step per pair
__device__ float g_C[(size_t)Nn * NC];       // per-step node GEMM output; reused as T (P x 64) at the end
__device__ __nv_bfloat16 g_Hhi[Nn * HD];
__device__ __nv_bfloat16 g_Hlo[Nn * HD];
__device__ __nv_bfloat16 g_Bhi[NC * HD];     // packed weights, [n][k] layout (384 x 64)
__device__ __nv_bfloat16 g_Blo[NC * HD];
__device__ float g_r[(size_t)Pp * 2 * HD];   // r assembled once by k_final
__device__ float g_a[Nn];                    // H[n] . Wfv[0:64]
__device__ float g_b[Nn];                    // H[n] . Wfv[64:128]
__device__ int   g_deg[Nn];
__device__ float g_dinv[Nn];
__device__ int   g_off[Nn + 1];
__device__ int   g_fill[Nn];
__device__ int   g_csr_row[NEe];
__device__ float g_csr_norm[NEe];

// ---------------- HMMA step GEMM: C[Nn x 384] = H @ Bpacked ----------------
// bf16x3 split: C = Ahi*Bhi + Ahi*Blo + Alo*Bhi  (fp32 accumulate)
// CTA tile: 128 rows x 192 cols, 512 threads (16 warps, 4m x 4n), warp tile 32 x 48.
// SMEM: padded row stride 72 bf16 (144 B) -> conflict-free fragment LDS.
#define S_AHI 0
#define S_ALO 18432                 // 128*144
#define S_BHI 36864
#define S_BLO (36864 + 27648)       // 192*144
#define S_TOT (S_BLO + 27648)       // 92160

__device__ __forceinline__ void hmma(float* d, uint32_t a0, uint32_t a1,
                                     uint32_t a2, uint32_t a3,
                                     uint32_t b0, uint32_t b1) {
    asm volatile(
        "mma.sync.aligned.m16n8k16.row.col.f32.bf16.bf16.f32 "
        "{%0,%1,%2,%3}, {%4,%5,%6,%7}, {%8,%9}, {%0,%1,%2,%3};\n"
        : "+f"(d[0]), "+f"(d[1]), "+f"(d[2]), "+f"(d[3])
        : "r"(a0), "r"(a1), "r"(a2), "r"(a3), "r"(b0), "r"(b1));
}

__global__ __launch_bounds__(512, 1) void mma_step(
    const __nv_bfloat16* __restrict__ Ahi, const __nv_bfloat16* __restrict__ Alo) {
    extern __shared__ char sm[];
    const int tid = threadIdx.x;
    const int brow = blockIdx.x * 128;
    const int bcol = blockIdx.y * 192;

#pragma unroll
    for (int i = 0; i < 2; i++) {
        int idx = tid * 2 + i;
        int r = idx >> 3, c = idx & 7;
        int gr = brow + r;
        uint4 vh = make_uint4(0, 0, 0, 0), vl = make_uint4(0, 0, 0, 0);
        if (gr < Nn) {
            vh = *reinterpret_cast<const uint4*>(&Ahi[(size_t)gr * HD + c * 8]);
            vl = *reinterpret_cast<const uint4*>(&Alo[(size_t)gr * HD + c * 8]);
        }
        *reinterpret_cast<uint4*>(sm + S_AHI + r * 144 + c * 16) = vh;
        *reinterpret_cast<uint4*>(sm + S_ALO + r * 144 + c * 16) = vl;
    }
#pragma unroll
    for (int i = 0; i < 3; i++) {
        int idx = tid * 3 + i;
        int r = idx >> 3, c = idx & 7;
        *reinterpret_cast<uint4*>(sm + S_BHI + r * 144 + c * 16) =
            *reinterpret_cast<const uint4*>(&g_Bhi[(size_t)(bcol + r) * HD + c * 8]);
        *reinterpret_cast<uint4*>(sm + S_BLO + r * 144 + c * 16) =
            *reinterpret_cast<const uint4*>(&g_Blo[(size_t)(bcol + r) * HD + c * 8]);
    }
    __syncthreads();

    const int wid = tid >> 5, lane = tid & 31;
    const int wm = wid >> 2, wn = wid & 3;
    const int g = lane >> 2, t = lane & 3;

    float acc[2][6][4];
#pragma unroll
    for (int mt = 0; mt < 2; mt++)
#pragma unroll
        for (int nt = 0; nt < 6; nt++)
#pragma unroll
            for (int q = 0; q < 4; q++) acc[mt][nt][q] = 0.f;

#pragma unroll
    for (int ab = 0; ab < 3; ab++) {
        const char* Ab = sm + ((ab == 2) ? S_ALO : S_AHI);
        const char* Bb = sm + ((ab == 1) ? S_BLO : S_BHI);
#pragma unroll
        for (int kc = 0; kc < 4; kc++) {
            int kb = kc * 32 + t * 4;
            uint32_t bf[6][2];
#pragma unroll
            for (int nt = 0; nt < 6; nt++) {
                int nr = wn * 48 + nt * 8 + g;
                bf[nt][0] = *reinterpret_cast<const uint32_t*>(Bb + nr * 144 + kb);
                bf[nt][1] = *reinterpret_cast<const uint32_t*>(Bb + nr * 144 + kb + 16);
            }
#pragma unroll
            for (int mt = 0; mt < 2; mt++) {
                int r0 = wm * 32 + mt * 16 + g;
                uint32_t a0 = *reinterpret_cast<const uint32_t*>(Ab + r0 * 144 + kb);
                uint32_t a1 = *reinterpret_cast<const uint32_t*>(Ab + (r0 + 8) * 144 + kb);
                uint32_t a2 = *reinterpret_cast<const uint32_t*>(Ab + r0 * 144 + kb + 16);
                uint32_t a3 = *reinterpret_cast<const uint32_t*>(Ab + (r0 + 8) * 144 + kb + 16);
#pragma unroll
                for (int nt = 0; nt < 6; nt++)
                    hmma(acc[mt][nt], a0, a1, a2, a3, bf[nt][0], bf[nt][1]);
            }
        }
    }

#pragma unroll
    for (int mt = 0; mt < 2; mt++) {
#pragma unroll
        for (int nt = 0; nt < 6; nt++) {
            int row = brow + wm * 32 + mt * 16 + g;
            int col = bcol + wn * 48 + nt * 8 + 2 * t;
            if (row < Nn) {
                float2 v = make_float2(acc[mt][nt][0], acc[mt][nt][1]);
                *reinterpret_cast<float2*>(&g_C[(size_t)row * NC + col]) = v;
            }
            if (row + 8 < Nn) {
                float2 v = make_float2(acc[mt][nt][2], acc[mt][nt][3]);
                *reinterpret_cast<float2*>(&g_C[(size_t)(row + 8) * NC + col]) = v;
            }
        }
    }
}

// ---------------- weight packing ----------------
__global__ void k_prepB(const float* __restrict__ Om, const float* __restrict__ Ws,
                        const float* __restrict__ Wfc1) {
    int i = blockIdx.x * blockDim.x + threadIdx.x;
    if (i >= HD * NC) return;
    int k = i / NC, j = i % NC;
    float v;
    if (j < 64)       v = Om[k * 64 + j] - Om[j * 64 + k];
    else if (j < 128) { int jj = j - 64; v = 0.5f * (Ws[k * 64 + jj] + Ws[jj * 64 + k]); }
    else if (j < 256) v = Wfc1[k * 128 + (j - 128)];
    else              v = Wfc1[(64 + k) * 128 + (j - 256)];
    __nv_bfloat16 hi = __float2bfloat16(v);
    __nv_bfloat16 lo = __float2bfloat16(v - __bfloat162float(hi));
    g_Bhi[(size_t)j * HD + k] = hi;
    g_Blo[(size_t)j * HD + k] = lo;
}

// ---------------- graph preprocessing ----------------
__global__ void k_init() {
    int i = blockIdx.x * blockDim.x + threadIdx.x;
    if (i < Nn) { g_deg[i] = 1; g_fill[i] = 0; }
}

__global__ void k_deg(const int* __restrict__ ei) {
    int e = blockIdx.x * blockDim.x + threadIdx.x;
    if (e < Ee) atomicAdd(&g_deg[ei[Ee + e]], 1);
}

__global__ void k_dinv() {
    int n = blockIdx.x * blockDim.x + threadIdx.x;
    if (n < Nn) g_dinv[n] = rsqrtf((float)g_deg[n]);
}

__global__ void k_scan() {
    __shared__ int sh[1024];
    __shared__ int carry_s;
    int t = threadIdx.x;
    if (t == 0) carry_s = 0;
    __syncthreads();
    for (int base = 0; base < Nn; base += 1024) {
        int v = (base + t < Nn) ? g_deg[base + t] : 0;
        int x = v;
        for (int off = 1; off < 1024; off <<= 1) {
            sh[t] = x; __syncthreads();
            if (t >= off) x += sh[t - off];
            __syncthreads();
        }
        int carry = carry_s;
        if (base + t < Nn) g_off[base + t] = carry + x - v;
        __syncthreads();
        if (t == 1023) carry_s = carry + x;
        __syncthreads();
    }
    if (t == 0) g_off[Nn] = carry_s;
}

__global__ void k_fill(const int* __restrict__ ei) {
    int e = blockIdx.x * blockDim.x + threadIdx.x;
    if (e >= NEe) return;
    int r_, c_;
    if (e < Ee) { r_ = ei[e]; c_ = ei[Ee + e]; }
    else        { r_ = c_ = e - Ee; }
    int pos = g_off[c_] + atomicAdd(&g_fill[c_], 1);
    g_csr_row[pos]  = r_;
    g_csr_norm[pos] = g_dinv[r_] * g_dinv[c_];
}

// ---------------- scalar SGEMM (H0 and final projection) ----------------
#define BMt 64
#define BNt 64
#define BKt 16
#define TMt 4
#define TNt 8
__global__ __launch_bounds__(128) void sgemm(const float* __restrict__ A,
                                             const float* __restrict__ B,
                                             float* __restrict__ Cc,
                                             int M, int K, int NCb, int act) {
    __shared__ float As[BKt][BMt];
    __shared__ float Bs[BKt][BNt];
    int block_row = blockIdx.y * BMt;
    int block_col = blockIdx.x * BNt;
    int tid = threadIdx.x;
    int ty = tid >> 3;
    int tx = tid & 7;
    int row0 = ty * TMt;
    int col0 = tx * TNt;
    float acc[TMt][TNt];
#pragma unroll
    for (int i = 0; i < TMt; i++)
#pragma unroll
        for (int j = 0; j < TNt; j++) acc[i][j] = 0.f;

    for (int k0 = 0; k0 < K; k0 += BKt) {
#pragma unroll
        for (int t = 0; t < 2; t++) {
            int idx = tid * 2 + t;
            int r = idx >> 2;
            int c4 = (idx & 3) * 4;
            int gr = block_row + r;
            float4 v = make_float4(0.f, 0.f, 0.f, 0.f);
            if (gr < M) v = *reinterpret_cast<const float4*>(&A[(size_t)gr * K + k0 + c4]);
            As[c4 + 0][r] = v.x; As[c4 + 1][r] = v.y;
            As[c4 + 2][r] = v.z; As[c4 + 3][r] = v.w;
        }
#pragma unroll
        for (int t = 0; t < 2; t++) {
            int idx = tid * 2 + t;
            int k = idx >> 4;
            int n4 = (idx & 15) * 4;
            float4 v = *reinterpret_cast<const float4*>(&B[(size_t)(k0 + k) * NCb + block_col + n4]);
            *reinterpret_cast<float4*>(&Bs[k][n4]) = v;
        }
        __syncthreads();
#pragma unroll
        for (int k = 0; k < BKt; k++) {
            float4 a4  = *reinterpret_cast<const float4*>(&As[k][row0]);
            float4 b4a = *reinterpret_cast<const float4*>(&Bs[k][col0]);
            float4 b4b = *reinterpret_cast<const float4*>(&Bs[k][col0 + 4]);
            float av[TMt] = {a4.x, a4.y, a4.z, a4.w};
            float bv[TNt] = {b4a.x, b4a.y, b4a.z, b4a.w, b4b.x, b4b.y, b4b.z, b4b.w};
#pragma unroll
            for (int i = 0; i < TMt; i++)
#pragma unroll
                for (int j = 0; j < TNt; j++)
                    acc[i][j] += av[i] * bv[j];
        }
        __syncthreads();
    }
#pragma unroll
    for (int i = 0; i < TMt; i++) {
        int gr = block_row + row0 + i;
        if (gr < M) {
#pragma unroll
            for (int j = 0; j < TNt; j++) {
                float v = acc[i][j];
                if (act) v = fmaxf(v, 0.f);
                Cc[(size_t)gr * NCb + block_col + col0 + j] = v;
            }
        }
    }
}

// ---------------- H -> bf16 hi/lo conversion + H0 snapshot ----------------
__global__ void k_h2b() {
    int i = blockIdx.x * blockDim.x + threadIdx.x;
    if (i >= Nn * HD) return;
    float x = g_H[i];
    g_H0[i] = x;
    __nv_bfloat16 hi = __float2bfloat16(x);
    g_Hhi[i] = hi;
    g_Hlo[i] = __float2bfloat16(x - __bfloat162float(hi));
}

// ---------------- per-node: sym gather, dH (-> slab l), nu partials, H update ----------------
__global__ __launch_bounds__(256) void k_node(const float* __restrict__ Wfv, int l) {
    int warp = (blockIdx.x * blockDim.x + threadIdx.x) >> 5;
    int lane = threadIdx.x & 31;
    if (warp >= Nn) return;
    int n = warp;
    int beg = g_off[n], end = g_off[n + 1];
    float s0 = 0.f, s1 = 0.f;
    for (int i = beg; i < end; i++) {
        int rs = g_csr_row[i];
        float w = g_csr_norm[i];
        const float* Mrow = &g_C[(size_t)rs * NC + 64];
        s0 += Mrow[lane] * w;
        s1 += Mrow[lane + 32] * w;
    }
    float a0 = g_C[(size_t)n * NC + lane];
    float a1 = g_C[(size_t)n * NC + 32 + lane];
    float dh0 = fmaxf(tanhf(s0 - fmaxf(a0, 0.f)), 0.f);
    float dh1 = fmaxf(tanhf(s1 - fmaxf(a1, 0.f)), 0.f);
    float* slab = &g_dHall[(size_t)l * Nn * HD];
    slab[n * HD + lane]      = dh0;
    slab[n * HD + lane + 32] = dh1;
    // nu partials from OLD H
    float h0 = g_H[n * HD + lane], h1 = g_H[n * HD + lane + 32];
    float pa = h0 * Wfv[lane]      + h1 * Wfv[lane + 32];
    float pb = h0 * Wfv[64 + lane] + h1 * Wfv[96 + lane];
#pragma unroll
    for (int o = 16; o > 0; o >>= 1) {
        pa += __shfl_xor_sync(0xffffffffu, pa, o);
        pb += __shfl_xor_sync(0xffffffffu, pb, o);
    }
    if (lane == 0) { g_a[n] = pa; g_b[n] = pb; }
    // H update in place + bf16 hi/lo emit for next step's MMA
    float hn0 = h0 + dh0, hn1 = h1 + dh1;
    g_H[n * HD + lane]      = hn0;
    g_H[n * HD + lane + 32] = hn1;
    __nv_bfloat16 hi0 = __float2bfloat16(hn0);
    __nv_bfloat16 hi1 = __float2bfloat16(hn1);
    g_Hhi[n * HD + lane]      = hi0;
    g_Hhi[n * HD + lane + 32] = hi1;
    g_Hlo[n * HD + lane]      = __float2bfloat16(hn0 - __bfloat162float(hi0));
    g_Hlo[n * HD + lane + 32] = __float2bfloat16(hn1 - __bfloat162float(hi1));
}

// ---------------- per-pair: tau only ----------------
__global__ __launch_bounds__(256) void k_pair_lite(const int* __restrict__ pairs,
                                                   const float* __restrict__ gum,
                                                   const float* __restrict__ Wfc2,
                                                   int l) {
    int warp = (blockIdx.x * blockDim.x + threadIdx.x) >> 5;
    int lane = threadIdx.x & 31;
    if (warp >= Pp) return;
    int p = warp;
    int s = pairs[2 * p], d = pairs[2 * p + 1];
    const float* Us = &g_C[(size_t)s * NC + 128];
    const float* Vd = &g_C[(size_t)d * NC + 256];
    float l0 = 0.f, l1 = 0.f;
#pragma unroll
    for (int i = 0; i < 4; i++) {
        int j = lane + 32 * i;
        float hv = fmaxf(Us[j] + Vd[j], 0.f);
        l0 += hv * Wfc2[2 * j];
        l1 += hv * Wfc2[2 * j + 1];
    }
#pragma unroll
    for (int o = 16; o > 0; o >>= 1) {
        l0 += __shfl_xor_sync(0xffffffffu, l0, o);
        l1 += __shfl_xor_sync(0xffffffffu, l1, o);
    }
    if (lane == 0) {
        float z  = g_a[s] + g_b[d];
        float nu = fmaxf(z, 0.f) + log1pf(expf(-fabsf(z))) + 1.0f;   // softplus + NU0
        float g0 = gum[((size_t)l * Pp + p) * 2];
        float g1 = gum[((size_t)l * Pp + p) * 2 + 1];
        float diff = ((l1 + g1) - (l0 + g0)) / nu;
        g_tau[(size_t)l * Pp + p] = 1.f / (1.f + expf(diff));
    }
}

// ---------------- final: assemble r in registers, write r + ts ----------------
__global__ __launch_bounds__(256) void k_final(const int* __restrict__ pairs,
                                               float* __restrict__ out) {
    int warp = (blockIdx.x * blockDim.x + threadIdx.x) >> 5;
    int lane = threadIdx.x & 31;
    if (warp >= Pp) return;
    int p = warp;
    int s = pairs[2 * p], d = pairs[2 * p + 1];
    float r0 = g_H0[s * HD + lane];
    float r1 = g_H0[s * HD + lane + 32];
    float r2 = g_H0[d * HD + lane];
    float r3 = g_H0[d * HD + lane + 32];
    // lane < 20 holds tau for step `lane`
    float tval = (lane < Ll) ? g_tau[(size_t)lane * Pp + p] : 0.f;
    float ts = 0.f;
#pragma unroll
    for (int l = 0; l < Ll; l++) {
        float tau = __shfl_sync(0xffffffffu, tval, l);
        const float* slab = &g_dHall[(size_t)l * Nn * HD];
        r0 += tau * slab[s * HD + lane];
        r1 += tau * slab[s * HD + lane + 32];
        r2 += tau * slab[d * HD + lane];
        r3 += tau * slab[d * HD + lane + 32];
        ts += tau;
    }
    float* rp = &g_r[(size_t)p * 2 * HD];
    rp[lane]       = r0;
    rp[lane + 32]  = r1;
    rp[lane + 64]  = r2;
    rp[lane + 96]  = r3;
    if (lane == 0) out[Pp + p] = ts;
}

// ---------------- final scores ----------------
__global__ __launch_bounds__(256) void k_score(const float* __restrict__ Wp2,
                                               float* __restrict__ out) {
    int warp = (blockIdx.x * blockDim.x + threadIdx.x) >> 5;
    int lane = threadIdx.x & 31;
    if (warp >= Pp) return;
    int p = warp;
    float t0 = g_C[(size_t)p * 64 + 2 * lane];
    float t1 = g_C[(size_t)p * 64 + 2 * lane + 1];
    float acc = t0 * Wp2[2 * lane] + t1 * Wp2[2 * lane + 1];
#pragma unroll
    for (int o = 16; o > 0; o >>= 1) acc += __shfl_xor_sync(0xffffffffu, acc, o);
    if (lane == 0) out[p] = acc;
}

// ---------------- host ----------------
extern "C" void kernel_launch(void* const* d_in, const int* in_sizes, int n_in,
                              void* d_out, int out_size) {
    const float* x    = (const float*)d_in[0];
    const int*   ei   = (const int*)d_in[1];
    const int*   pairs= (const int*)d_in[2];
    const float* gum  = (const float*)d_in[3];
    const float* Wenc = (const float*)d_in[4];
    const float* Om   = (const float*)d_in[5];
    const float* Wsr  = (const float*)d_in[6];
    const float* Wfc1 = (const float*)d_in[7];
    const float* Wfc2 = (const float*)d_in[8];
    const float* Wfv  = (const float*)d_in[9];
    const float* Wp1  = (const float*)d_in[10];
    const float* Wp2  = (const float*)d_in[11];
    float* out = (float*)d_out;

    void *pH, *pC, *pR, *pHhi, *pHlo;
    cudaGetSymbolAddress(&pH, g_H);
    cudaGetSymbolAddress(&pC, g_C);
    cudaGetSymbolAddress(&pR, g_r);
    cudaGetSymbolAddress(&pHhi, g_Hhi);
    cudaGetSymbolAddress(&pHlo, g_Hlo);
    float* H_ = (float*)pH;
    float* C_ = (float*)pC;
    float* R_ = (float*)pR;
    const __nv_bfloat16* Hhi_ = (const __nv_bfloat16*)pHhi;
    const __nv_bfloat16* Hlo_ = (const __nv_bfloat16*)pHlo;

    cudaFuncSetAttribute(mma_step, cudaFuncAttributeMaxDynamicSharedMemorySize, S_TOT);

    // weights + graph prep
    k_prepB<<<(HD * NC + 255) / 256, 256>>>(Om, Wsr, Wfc1);
    k_init<<<(Nn + 255) / 256, 256>>>();
    k_deg<<<(Ee + 255) / 256, 256>>>(ei);
    k_dinv<<<(Nn + 255) / 256, 256>>>();
    k_scan<<<1, 1024>>>();
    k_fill<<<(NEe + 255) / 256, 256>>>(ei);

    // H0 = relu(x @ W_enc); snapshot + bf16 split
    sgemm<<<dim3(1, (Nn + BMt - 1) / BMt), 128>>>(x, Wenc, H_, Nn, INF, HD, 1);
    k_h2b<<<(Nn * HD + 255) / 256, 256>>>();

    dim3 grid_mma((Nn + 127) / 128, 2);
    for (int l = 0; l < Ll; l++) {
        mma_step<<<grid_mma, 512, S_TOT>>>(Hhi_, Hlo_);
        k_node<<<(Nn * 32) / 256, 256>>>(Wfv, l);
        k_pair_lite<<<(Pp * 32) / 256, 256>>>(pairs, gum, Wfc2, l);
    }

    // assemble r (registers -> g_r) + ts, then T = relu(r @ W_p1), scores
    k_final<<<(Pp * 32) / 256, 256>>>(pairs, out);
    sgemm<<<dim3(1, (Pp + BMt - 1) / BMt), 128>>>(R_, Wp1, C_, Pp, 2 * HD, HD, 1);
    k_score<<<(Pp * 32) / 256, 256>>>(Wp2, out);
}

// round 5
// speedup vs baseline: 1.8968x; 1.0883x over previous
#include <cuda_runtime.h>
#include <cuda_bf16.h>
#include <math.h>
#include <stdint.h>

// Problem constants
#define Nn   20000
#define Ee   320000
#define Pp   50000
#define Ll   20
#define INF  128
#define HD   64
#define NEe  (Ee + Nn)
#define NC   384   // packed node-GEMM output cols: [anti_pre(64)|M(64)|U(128)|V(128)]

// ---------------- device scratch (no allocation allowed) ----------------
__device__ float g_H[Nn * HD];
__device__ float g_H0[Nn * HD];
__device__ float g_dHall[(size_t)Ll * Nn * HD];   // all step dH slabs (102.4 MB)
__device__ float g_tau[(size_t)Ll * Pp];          // tau per step per pair
__device__ float g_C[(size_t)Nn * NC];            // step GEMM out; reused as T (P x 64)
__device__ __nv_bfloat16 g_Hhi[Nn * HD];
__device__ __nv_bfloat16 g_Hlo[Nn * HD];
__device__ __nv_bfloat16 g_Bhi[NC * HD];          // packed loop weights [n][k] (384 x 64)
__device__ __nv_bfloat16 g_Blo[NC * HD];
__device__ __nv_bfloat16 g_xhi[Nn * INF];         // x split (20000 x 128)
__device__ __nv_bfloat16 g_xlo[Nn * INF];
__device__ __nv_bfloat16 g_Wehi[HD * INF];        // Wenc packed [n][k] (64 x 128)
__device__ __nv_bfloat16 g_Welo[HD * INF];
__device__ __nv_bfloat16 g_Wp1hi[HD * INF];       // Wp1 packed [n][k] (64 x 128)
__device__ __nv_bfloat16 g_Wp1lo[HD * INF];
__device__ __nv_bfloat16 g_rhi[(size_t)Pp * 2 * HD];  // r split (50000 x 128)
__device__ __nv_bfloat16 g_rlo[(size_t)Pp * 2 * HD];
__device__ float g_a[2][Nn];                      // H[n].Wfv[0:64], double-buffered
__device__ float g_b[2][Nn];                      // H[n].Wfv[64:128]
__device__ int   g_deg[Nn];
__device__ float g_dinv[Nn];
__device__ int   g_off[Nn + 1];
__device__ int   g_fill[Nn];
__device__ int   g_csr_row[NEe];
__device__ float g_csr_norm[NEe];

// ---------------- HMMA primitive ----------------
__device__ __forceinline__ void hmma(float* d, uint32_t a0, uint32_t a1,
                                     uint32_t a2, uint32_t a3,
                                     uint32_t b0, uint32_t b1) {
    asm volatile(
        "mma.sync.aligned.m16n8k16.row.col.f32.bf16.bf16.f32 "
        "{%0,%1,%2,%3}, {%4,%5,%6,%7}, {%8,%9}, {%0,%1,%2,%3};\n"
        : "+f"(d[0]), "+f"(d[1]), "+f"(d[2]), "+f"(d[3])
        : "r"(a0), "r"(a1), "r"(a2), "r"(a3), "r"(b0), "r"(b1));
}

// ---------------- loop step GEMM: C[Nn x 384] = H @ Bpacked (bf16x3) ----------------
// CTA tile 128 x 192, 512 threads (16 warps, 4m x 4n), warp tile 32 x 48.
// SMEM row stride 144 B -> bank = 4g+t, conflict-free fragment LDS.
#define S_AHI 0
#define S_ALO 18432                 // 128*144
#define S_BHI 36864
#define S_BLO (36864 + 27648)       // 192*144
#define S_TOT (S_BLO + 27648)       // 92160

__global__ __launch_bounds__(512, 1) void mma_step(
    const __nv_bfloat16* __restrict__ Ahi, const __nv_bfloat16* __restrict__ Alo) {
    extern __shared__ char sm[];
    const int tid = threadIdx.x;
    const int brow = blockIdx.x * 128;
    const int bcol = blockIdx.y * 192;

#pragma unroll
    for (int i = 0; i < 2; i++) {
        int idx = tid * 2 + i;
        int r = idx >> 3, c = idx & 7;
        int gr = brow + r;
        uint4 vh = make_uint4(0, 0, 0, 0), vl = make_uint4(0, 0, 0, 0);
        if (gr < Nn) {
            vh = *reinterpret_cast<const uint4*>(&Ahi[(size_t)gr * HD + c * 8]);
            vl = *reinterpret_cast<const uint4*>(&Alo[(size_t)gr * HD + c * 8]);
        }
        *reinterpret_cast<uint4*>(sm + S_AHI + r * 144 + c * 16) = vh;
        *reinterpret_cast<uint4*>(sm + S_ALO + r * 144 + c * 16) = vl;
    }
#pragma unroll
    for (int i = 0; i < 3; i++) {
        int idx = tid * 3 + i;
        int r = idx >> 3, c = idx & 7;
        *reinterpret_cast<uint4*>(sm + S_BHI + r * 144 + c * 16) =
            *reinterpret_cast<const uint4*>(&g_Bhi[(size_t)(bcol + r) * HD + c * 8]);
        *reinterpret_cast<uint4*>(sm + S_BLO + r * 144 + c * 16) =
            *reinterpret_cast<const uint4*>(&g_Blo[(size_t)(bcol + r) * HD + c * 8]);
    }
    __syncthreads();

    const int wid = tid >> 5, lane = tid & 31;
    const int wm = wid >> 2, wn = wid & 3;
    const int g = lane >> 2, t = lane & 3;

    float acc[2][6][4];
#pragma unroll
    for (int mt = 0; mt < 2; mt++)
#pragma unroll
        for (int nt = 0; nt < 6; nt++)
#pragma unroll
            for (int q = 0; q < 4; q++) acc[mt][nt][q] = 0.f;

#pragma unroll
    for (int ab = 0; ab < 3; ab++) {
        const char* Ab = sm + ((ab == 2) ? S_ALO : S_AHI);
        const char* Bb = sm + ((ab == 1) ? S_BLO : S_BHI);
#pragma unroll
        for (int kc = 0; kc < 4; kc++) {
            int kb = kc * 32 + t * 4;
            uint32_t bf[6][2];
#pragma unroll
            for (int nt = 0; nt < 6; nt++) {
                int nr = wn * 48 + nt * 8 + g;
                bf[nt][0] = *reinterpret_cast<const uint32_t*>(Bb + nr * 144 + kb);
                bf[nt][1] = *reinterpret_cast<const uint32_t*>(Bb + nr * 144 + kb + 16);
            }
#pragma unroll
            for (int mt = 0; mt < 2; mt++) {
                int r0 = wm * 32 + mt * 16 + g;
                uint32_t a0 = *reinterpret_cast<const uint32_t*>(Ab + r0 * 144 + kb);
                uint32_t a1 = *reinterpret_cast<const uint32_t*>(Ab + (r0 + 8) * 144 + kb);
                uint32_t a2 = *reinterpret_cast<const uint32_t*>(Ab + r0 * 144 + kb + 16);
                uint32_t a3 = *reinterpret_cast<const uint32_t*>(Ab + (r0 + 8) * 144 + kb + 16);
#pragma unroll
                for (int nt = 0; nt < 6; nt++)
                    hmma(acc[mt][nt], a0, a1, a2, a3, bf[nt][0], bf[nt][1]);
            }
        }
    }

#pragma unroll
    for (int mt = 0; mt < 2; mt++) {
#pragma unroll
        for (int nt = 0; nt < 6; nt++) {
            int row = brow + wm * 32 + mt * 16 + g;
            int col = bcol + wn * 48 + nt * 8 + 2 * t;
            if (row < Nn) {
                float2 v = make_float2(acc[mt][nt][0], acc[mt][nt][1]);
                *reinterpret_cast<float2*>(&g_C[(size_t)row * NC + col]) = v;
            }
            if (row + 8 < Nn) {
                float2 v = make_float2(acc[mt][nt][2], acc[mt][nt][3]);
                *reinterpret_cast<float2*>(&g_C[(size_t)(row + 8) * NC + col]) = v;
            }
        }
    }
}

// ---------------- generic HMMA GEMM, N=64: C[M x 64] = act(A[M x K] @ B) ----------------
// A hi/lo row-major [M][K]; B hi/lo packed [n][k] (64 x K). CTA tile 128 x 64,
// 512 threads (16 warps, 4m x 4n), warp tile 32 x 16. Row stride K*2+16 bytes.
__global__ __launch_bounds__(512, 1) void mma_gemm64(
    const __nv_bfloat16* __restrict__ Ahi, const __nv_bfloat16* __restrict__ Alo,
    const __nv_bfloat16* __restrict__ Bhi, const __nv_bfloat16* __restrict__ Blo,
    float* __restrict__ C, int M, int K, int act) {
    extern __shared__ char sm[];
    const int tid = threadIdx.x;
    const int brow = blockIdx.x * 128;
    const int SB = K * 2 + 16;
    char* Ah = sm;
    char* Al = sm + 128 * SB;
    char* Bh = sm + 256 * SB;
    char* Bl = sm + 320 * SB;
    const int ku4 = K >> 3;

    for (int idx = tid; idx < 128 * ku4; idx += 512) {
        int r = idx / ku4, c = idx % ku4;
        int gr = brow + r;
        uint4 vh = make_uint4(0, 0, 0, 0), vl = make_uint4(0, 0, 0, 0);
        if (gr < M) {
            vh = *reinterpret_cast<const uint4*>(&Ahi[(size_t)gr * K + c * 8]);
            vl = *reinterpret_cast<const uint4*>(&Alo[(size_t)gr * K + c * 8]);
        }
        *reinterpret_cast<uint4*>(Ah + r * SB + c * 16) = vh;
        *reinterpret_cast<uint4*>(Al + r * SB + c * 16) = vl;
    }
    for (int idx = tid; idx < 64 * ku4; idx += 512) {
        int r = idx / ku4, c = idx % ku4;
        *reinterpret_cast<uint4*>(Bh + r * SB + c * 16) =
            *reinterpret_cast<const uint4*>(&Bhi[(size_t)r * K + c * 8]);
        *reinterpret_cast<uint4*>(Bl + r * SB + c * 16) =
            *reinterpret_cast<const uint4*>(&Blo[(size_t)r * K + c * 8]);
    }
    __syncthreads();

    const int wid = tid >> 5, lane = tid & 31;
    const int wm = wid >> 2, wn = wid & 3;
    const int g = lane >> 2, t = lane & 3;
    const int KC = K >> 4;

    float acc[2][2][4];
#pragma unroll
    for (int mt = 0; mt < 2; mt++)
#pragma unroll
        for (int nt = 0; nt < 2; nt++)
#pragma unroll
            for (int q = 0; q < 4; q++) acc[mt][nt][q] = 0.f;

#pragma unroll
    for (int ab = 0; ab < 3; ab++) {
        const char* A_ = (ab == 2) ? Al : Ah;
        const char* B_ = (ab == 1) ? Bl : Bh;
        for (int kc = 0; kc < KC; kc++) {
            int kb = kc * 32 + t * 4;
            uint32_t bf[2][2];
#pragma unroll
            for (int nt = 0; nt < 2; nt++) {
                int nr = wn * 16 + nt * 8 + g;
                bf[nt][0] = *reinterpret_cast<const uint32_t*>(B_ + nr * SB + kb);
                bf[nt][1] = *reinterpret_cast<const uint32_t*>(B_ + nr * SB + kb + 16);
            }
#pragma unroll
            for (int mt = 0; mt < 2; mt++) {
                int r0 = wm * 32 + mt * 16 + g;
                uint32_t a0 = *reinterpret_cast<const uint32_t*>(A_ + r0 * SB + kb);
                uint32_t a1 = *reinterpret_cast<const uint32_t*>(A_ + (r0 + 8) * SB + kb);
                uint32_t a2 = *reinterpret_cast<const uint32_t*>(A_ + r0 * SB + kb + 16);
                uint32_t a3 = *reinterpret_cast<const uint32_t*>(A_ + (r0 + 8) * SB + kb + 16);
#pragma unroll
                for (int nt = 0; nt < 2; nt++)
                    hmma(acc[mt][nt], a0, a1, a2, a3, bf[nt][0], bf[nt][1]);
            }
        }
    }

#pragma unroll
    for (int mt = 0; mt < 2; mt++) {
#pragma unroll
        for (int nt = 0; nt < 2; nt++) {
            int row = brow + wm * 32 + mt * 16 + g;
            int col = wn * 16 + nt * 8 + 2 * t;
            float v0 = acc[mt][nt][0], v1 = acc[mt][nt][1];
            float v2 = acc[mt][nt][2], v3 = acc[mt][nt][3];
            if (act) {
                v0 = fmaxf(v0, 0.f); v1 = fmaxf(v1, 0.f);
                v2 = fmaxf(v2, 0.f); v3 = fmaxf(v3, 0.f);
            }
            if (row < M)
                *reinterpret_cast<float2*>(&C[(size_t)row * 64 + col]) = make_float2(v0, v1);
            if (row + 8 < M)
                *reinterpret_cast<float2*>(&C[(size_t)(row + 8) * 64 + col]) = make_float2(v2, v3);
        }
    }
}

// ---------------- weight packing ----------------
__global__ void k_prepB(const float* __restrict__ Om, const float* __restrict__ Ws,
                        const float* __restrict__ Wfc1) {
    int i = blockIdx.x * blockDim.x + threadIdx.x;
    if (i >= HD * NC) return;
    int k = i / NC, j = i % NC;
    float v;
    if (j < 64)       v = Om[k * 64 + j] - Om[j * 64 + k];
    else if (j < 128) { int jj = j - 64; v = 0.5f * (Ws[k * 64 + jj] + Ws[jj * 64 + k]); }
    else if (j < 256) v = Wfc1[k * 128 + (j - 128)];
    else              v = Wfc1[(64 + k) * 128 + (j - 256)];
    __nv_bfloat16 hi = __float2bfloat16(v);
    __nv_bfloat16 lo = __float2bfloat16(v - __bfloat162float(hi));
    g_Bhi[(size_t)j * HD + k] = hi;
    g_Blo[(size_t)j * HD + k] = lo;
}

// pack a (K x 64) row-major weight into [n][k] bf16 hi/lo (n = 0..63, k = 0..K-1)
__global__ void k_prepW(const float* __restrict__ src, int K,
                        __nv_bfloat16* __restrict__ dhi, __nv_bfloat16* __restrict__ dlo) {
    int i = blockIdx.x * blockDim.x + threadIdx.x;
    if (i >= K * HD) return;
    int k = i / HD, n = i % HD;
    float v = src[i];
    __nv_bfloat16 hi = __float2bfloat16(v);
    dhi[(size_t)n * K + k] = hi;
    dlo[(size_t)n * K + k] = __float2bfloat16(v - __bfloat162float(hi));
}

// ---------------- graph preprocessing ----------------
__global__ void k_init() {
    int i = blockIdx.x * blockDim.x + threadIdx.x;
    if (i < Nn) { g_deg[i] = 1; g_fill[i] = 0; }
}

__global__ void k_deg(const int* __restrict__ ei) {
    int e = blockIdx.x * blockDim.x + threadIdx.x;
    if (e < Ee) atomicAdd(&g_deg[ei[Ee + e]], 1);
}

__global__ void k_dinv() {
    int n = blockIdx.x * blockDim.x + threadIdx.x;
    if (n < Nn) g_dinv[n] = rsqrtf((float)g_deg[n]);
}

__global__ void k_scan() {
    __shared__ int sh[1024];
    __shared__ int carry_s;
    int t = threadIdx.x;
    if (t == 0) carry_s = 0;
    __syncthreads();
    for (int base = 0; base < Nn; base += 1024) {
        int v = (base + t < Nn) ? g_deg[base + t] : 0;
        int x = v;
        for (int off = 1; off < 1024; off <<= 1) {
            sh[t] = x; __syncthreads();
            if (t >= off) x += sh[t - off];
            __syncthreads();
        }
        int carry = carry_s;
        if (base + t < Nn) g_off[base + t] = carry + x - v;
        __syncthreads();
        if (t == 1023) carry_s = carry + x;
        __syncthreads();
    }
    if (t == 0) g_off[Nn] = carry_s;
}

__global__ void k_fill(const int* __restrict__ ei) {
    int e = blockIdx.x * blockDim.x + threadIdx.x;
    if (e >= NEe) return;
    int r_, c_;
    if (e < Ee) { r_ = ei[e]; c_ = ei[Ee + e]; }
    else        { r_ = c_ = e - Ee; }
    int pos = g_off[c_] + atomicAdd(&g_fill[c_], 1);
    g_csr_row[pos]  = r_;
    g_csr_norm[pos] = g_dinv[r_] * g_dinv[c_];
}

// ---------------- input conversions ----------------
__global__ void k_x2b(const float* __restrict__ x) {
    int i = blockIdx.x * blockDim.x + threadIdx.x;
    if (i >= Nn * INF) return;
    float v = x[i];
    __nv_bfloat16 hi = __float2bfloat16(v);
    g_xhi[i] = hi;
    g_xlo[i] = __float2bfloat16(v - __bfloat162float(hi));
}

__global__ void k_h2b() {
    int i = blockIdx.x * blockDim.x + threadIdx.x;
    if (i >= Nn * HD) return;
    float v = g_H[i];
    g_H0[i] = v;
    __nv_bfloat16 hi = __float2bfloat16(v);
    g_Hhi[i] = hi;
    g_Hlo[i] = __float2bfloat16(v - __bfloat162float(hi));
}

// a,b for step 0 from H0
__global__ __launch_bounds__(256) void k_ab(const float* __restrict__ Wfv) {
    int warp = (blockIdx.x * blockDim.x + threadIdx.x) >> 5;
    int lane = threadIdx.x & 31;
    if (warp >= Nn) return;
    float h0 = g_H[warp * HD + lane], h1 = g_H[warp * HD + lane + 32];
    float pa = h0 * Wfv[lane]      + h1 * Wfv[lane + 32];
    float pb = h0 * Wfv[64 + lane] + h1 * Wfv[96 + lane];
#pragma unroll
    for (int o = 16; o > 0; o >>= 1) {
        pa += __shfl_xor_sync(0xffffffffu, pa, o);
        pb += __shfl_xor_sync(0xffffffffu, pb, o);
    }
    if (lane == 0) { g_a[0][warp] = pa; g_b[0][warp] = pb; }
}

// ---------------- fused per-step kernel: node warps + pair warps ----------------
__global__ __launch_bounds__(256) void k_step(const int* __restrict__ pairs,
                                              const float* __restrict__ gum,
                                              const float* __restrict__ Wfc2,
                                              const float* __restrict__ Wfv,
                                              int l) {
    int warp = (blockIdx.x * blockDim.x + threadIdx.x) >> 5;
    int lane = threadIdx.x & 31;
    if (warp < Nn) {
        // ---- node path ----
        int n = warp;
        int beg = g_off[n], end = g_off[n + 1];
        float s0 = 0.f, s1 = 0.f;
        for (int i = beg; i < end; i++) {
            int rs = g_csr_row[i];
            float w = g_csr_norm[i];
            const float* Mrow = &g_C[(size_t)rs * NC + 64];
            s0 += Mrow[lane] * w;
            s1 += Mrow[lane + 32] * w;
        }
        float a0 = g_C[(size_t)n * NC + lane];
        float a1 = g_C[(size_t)n * NC + 32 + lane];
        float dh0 = fmaxf(tanhf(s0 - fmaxf(a0, 0.f)), 0.f);
        float dh1 = fmaxf(tanhf(s1 - fmaxf(a1, 0.f)), 0.f);
        float* slab = &g_dHall[(size_t)l * Nn * HD];
        slab[n * HD + lane]      = dh0;
        slab[n * HD + lane + 32] = dh1;
        // H update in place + bf16 hi/lo emit
        float hn0 = g_H[n * HD + lane] + dh0;
        float hn1 = g_H[n * HD + lane + 32] + dh1;
        g_H[n * HD + lane]      = hn0;
        g_H[n * HD + lane + 32] = hn1;
        __nv_bfloat16 hi0 = __float2bfloat16(hn0);
        __nv_bfloat16 hi1 = __float2bfloat16(hn1);
        g_Hhi[n * HD + lane]      = hi0;
        g_Hhi[n * HD + lane + 32] = hi1;
        g_Hlo[n * HD + lane]      = __float2bfloat16(hn0 - __bfloat162float(hi0));
        g_Hlo[n * HD + lane + 32] = __float2bfloat16(hn1 - __bfloat162float(hi1));
        // nu partials for NEXT step (from updated H)
        float pa = hn0 * Wfv[lane]      + hn1 * Wfv[lane + 32];
        float pb = hn0 * Wfv[64 + lane] + hn1 * Wfv[96 + lane];
#pragma unroll
        for (int o = 16; o > 0; o >>= 1) {
            pa += __shfl_xor_sync(0xffffffffu, pa, o);
            pb += __shfl_xor_sync(0xffffffffu, pb, o);
        }
        if (lane == 0) { g_a[(l + 1) & 1][n] = pa; g_b[(l + 1) & 1][n] = pb; }
    } else {
        // ---- pair path ----
        int p = warp - Nn;
        if (p >= Pp) return;
        int s = pairs[2 * p], d = pairs[2 * p + 1];
        const float* Us = &g_C[(size_t)s * NC + 128];
        const float* Vd = &g_C[(size_t)d * NC + 256];
        float l0 = 0.f, l1 = 0.f;
#pragma unroll
        for (int i = 0; i < 4; i++) {
            int j = lane + 32 * i;
            float hv = fmaxf(Us[j] + Vd[j], 0.f);
            l0 += hv * Wfc2[2 * j];
            l1 += hv * Wfc2[2 * j + 1];
        }
#pragma unroll
        for (int o = 16; o > 0; o >>= 1) {
            l0 += __shfl_xor_sync(0xffffffffu, l0, o);
            l1 += __shfl_xor_sync(0xffffffffu, l1, o);
        }
        if (lane == 0) {
            float z  = g_a[l & 1][s] + g_b[l & 1][d];
            float nu = fmaxf(z, 0.f) + log1pf(expf(-fabsf(z))) + 1.0f;
            float g0 = gum[((size_t)l * Pp + p) * 2];
            float g1 = gum[((size_t)l * Pp + p) * 2 + 1];
            float diff = ((l1 + g1) - (l0 + g0)) / nu;
            g_tau[(size_t)l * Pp + p] = 1.f / (1.f + expf(diff));
        }
    }
}

// ---------------- final: assemble r in registers -> bf16 hi/lo, write ts ----------------
__global__ __launch_bounds__(256) void k_final(const int* __restrict__ pairs,
                                               float* __restrict__ out) {
    int warp = (blockIdx.x * blockDim.x + threadIdx.x) >> 5;
    int lane = threadIdx.x & 31;
    if (warp >= Pp) return;
    int p = warp;
    int s = pairs[2 * p], d = pairs[2 * p + 1];
    float r0 = g_H0[s * HD + lane];
    float r1 = g_H0[s * HD + lane + 32];
    float r2 = g_H0[d * HD + lane];
    float r3 = g_H0[d * HD + lane + 32];
    float tval = (lane < Ll) ? g_tau[(size_t)lane * Pp + p] : 0.f;
    float ts = 0.f;
#pragma unroll
    for (int l = 0; l < Ll; l++) {
        float tau = __shfl_sync(0xffffffffu, tval, l);
        const float* slab = &g_dHall[(size_t)l * Nn * HD];
        r0 += tau * slab[s * HD + lane];
        r1 += tau * slab[s * HD + lane + 32];
        r2 += tau * slab[d * HD + lane];
        r3 += tau * slab[d * HD + lane + 32];
        ts += tau;
    }
    size_t base = (size_t)p * 2 * HD;
    float vals[4] = {r0, r1, r2, r3};
#pragma unroll
    for (int q = 0; q < 4; q++) {
        __nv_bfloat16 hi = __float2bfloat16(vals[q]);
        g_rhi[base + lane + 32 * q] = hi;
        g_rlo[base + lane + 32 * q] = __float2bfloat16(vals[q] - __bfloat162float(hi));
    }
    if (lane == 0) out[Pp + p] = ts;
}

// ---------------- final scores ----------------
__global__ __launch_bounds__(256) void k_score(const float* __restrict__ Wp2,
                                               float* __restrict__ out) {
    int warp = (blockIdx.x * blockDim.x + threadIdx.x) >> 5;
    int lane = threadIdx.x & 31;
    if (warp >= Pp) return;
    int p = warp;
    float t0 = g_C[(size_t)p * 64 + 2 * lane];
    float t1 = g_C[(size_t)p * 64 + 2 * lane + 1];
    float acc = t0 * Wp2[2 * lane] + t1 * Wp2[2 * lane + 1];
#pragma unroll
    for (int o = 16; o > 0; o >>= 1) acc += __shfl_xor_sync(0xffffffffu, acc, o);
    if (lane == 0) out[p] = acc;
}

// ---------------- host ----------------
extern "C" void kernel_launch(void* const* d_in, const int* in_sizes, int n_in,
                              void* d_out, int out_size) {
    const float* x    = (const float*)d_in[0];
    const int*   ei   = (const int*)d_in[1];
    const int*   pairs= (const int*)d_in[2];
    const float* gum  = (const float*)d_in[3];
    const float* Wenc = (const float*)d_in[4];
    const float* Om   = (const float*)d_in[5];
    const float* Wsr  = (const float*)d_in[6];
    const float* Wfc1 = (const float*)d_in[7];
    const float* Wfc2 = (const float*)d_in[8];
    const float* Wfv  = (const float*)d_in[9];
    const float* Wp1  = (const float*)d_in[10];
    const float* Wp2  = (const float*)d_in[11];
    float* out = (float*)d_out;

    void *pH, *pC, *pHhi, *pHlo, *pXhi, *pXlo, *pWeh, *pWel, *pWph, *pWpl, *pRhi, *pRlo;
    cudaGetSymbolAddress(&pH, g_H);
    cudaGetSymbolAddress(&pC, g_C);
    cudaGetSymbolAddress(&pHhi, g_Hhi);
    cudaGetSymbolAddress(&pHlo, g_Hlo);
    cudaGetSymbolAddress(&pXhi, g_xhi);
    cudaGetSymbolAddress(&pXlo, g_xlo);
    cudaGetSymbolAddress(&pWeh, g_Wehi);
    cudaGetSymbolAddress(&pWel, g_Welo);
    cudaGetSymbolAddress(&pWph, g_Wp1hi);
    cudaGetSymbolAddress(&pWpl, g_Wp1lo);
    cudaGetSymbolAddress(&pRhi, g_rhi);
    cudaGetSymbolAddress(&pRlo, g_rlo);
    float* H_ = (float*)pH;
    float* C_ = (float*)pC;
    const __nv_bfloat16* Hhi_ = (const __nv_bfloat16*)pHhi;
    const __nv_bfloat16* Hlo_ = (const __nv_bfloat16*)pHlo;

    cudaFuncSetAttribute(mma_step, cudaFuncAttributeMaxDynamicSharedMemorySize, S_TOT);
    const int SM64 = 384 * (INF * 2 + 16);   // 104448 for K=128
    cudaFuncSetAttribute(mma_gemm64, cudaFuncAttributeMaxDynamicSharedMemorySize, SM64);

    // weights + graph prep + input conversion
    k_prepB<<<(HD * NC + 255) / 256, 256>>>(Om, Wsr, Wfc1);
    k_prepW<<<(INF * HD + 255) / 256, 256>>>(Wenc, INF, (__nv_bfloat16*)pWeh, (__nv_bfloat16*)pWel);
    k_prepW<<<(INF * HD + 255) / 256, 256>>>(Wp1, INF, (__nv_bfloat16*)pWph, (__nv_bfloat16*)pWpl);
    k_x2b<<<(Nn * INF + 255) / 256, 256>>>(x);
    k_init<<<(Nn + 255) / 256, 256>>>();
    k_deg<<<(Ee + 255) / 256, 256>>>(ei);
    k_dinv<<<(Nn + 255) / 256, 256>>>();
    k_scan<<<1, 1024>>>();
    k_fill<<<(NEe + 255) / 256, 256>>>(ei);

    // H0 = relu(x @ Wenc) via HMMA; snapshot + split; a,b for step 0
    mma_gemm64<<<(Nn + 127) / 128, 512, SM64>>>(
        (const __nv_bfloat16*)pXhi, (const __nv_bfloat16*)pXlo,
        (const __nv_bfloat16*)pWeh, (const __nv_bfloat16*)pWel, H_, Nn, INF, 1);
    k_h2b<<<(Nn * HD + 255) / 256, 256>>>();
    k_ab<<<(Nn * 32 + 255) / 256, 256>>>(Wfv);

    dim3 grid_mma((Nn + 127) / 128, 2);
    int step_blocks = ((Nn + Pp) * 32 + 255) / 256;
    for (int l = 0; l < Ll; l++) {
        mma_step<<<grid_mma, 512, S_TOT>>>(Hhi_, Hlo_);
        k_step<<<step_blocks, 256>>>(pairs, gum, Wfc2, Wfv, l);
    }

    // r (bf16 hi/lo) + ts, then T = relu(r @ Wp1) via HMMA, then scores
    k_final<<<(Pp * 32 + 255) / 256, 256>>>(pairs, out);
    mma_gemm64<<<(Pp + 127) / 128, 512, SM64>>>(
        (const __nv_bfloat16*)pRhi, (const __nv_bfloat16*)pRlo,
        (const __nv_bfloat16*)pWph, (const __nv_bfloat16*)pWpl, C_, Pp, INF, 1);
    k_score<<<(Pp * 32 + 255) / 256, 256>>>(Wp2, out);
}

// round 6
// speedup vs baseline: 1.9407x; 1.0232x over previous
#include <cuda_runtime.h>
#include <cuda_bf16.h>
#include <math.h>
#include <stdint.h>

// Problem constants
#define Nn   20000
#define Ee   320000
#define Pp   50000
#define Ll   20
#define INF  128
#define HD   64
#define NEe  (Ee + Nn)
#define NC   384   // packed node-GEMM output cols: [anti_pre(64)|M(64)|U(128)|V(128)]

// ---------------- device scratch (no allocation allowed) ----------------
__device__ float g_H[Nn * HD];
__device__ float g_H0[Nn * HD];
__device__ __nv_bfloat16 g_dHall[(size_t)Ll * Nn * HD];  // dH slabs, bf16 (51.2 MB)
__device__ float g_tau[(size_t)Ll * Pp];          // tau per step per pair
__device__ float g_C[(size_t)Nn * NC];            // step GEMM out; reused as T (P x 64)
__device__ __nv_bfloat16 g_Hhi[Nn * HD];
__device__ __nv_bfloat16 g_Hlo[Nn * HD];
__device__ __nv_bfloat16 g_Bhi[NC * HD];          // packed loop weights [n][k] (384 x 64)
__device__ __nv_bfloat16 g_Blo[NC * HD];
__device__ __nv_bfloat16 g_xhi[Nn * INF];         // x split (20000 x 128)
__device__ __nv_bfloat16 g_xlo[Nn * INF];
__device__ __nv_bfloat16 g_Wehi[HD * INF];        // Wenc packed [n][k] (64 x 128)
__device__ __nv_bfloat16 g_Welo[HD * INF];
__device__ __nv_bfloat16 g_Wp1hi[HD * INF];       // Wp1 packed [n][k] (64 x 128)
__device__ __nv_bfloat16 g_Wp1lo[HD * INF];
__device__ __nv_bfloat16 g_rhi[(size_t)Pp * 2 * HD];  // r split (50000 x 128)
__device__ __nv_bfloat16 g_rlo[(size_t)Pp * 2 * HD];
__device__ float g_a[2][Nn];                      // H[n].Wfv[0:64], double-buffered
__device__ float g_b[2][Nn];                      // H[n].Wfv[64:128]
__device__ int   g_deg[Nn];
__device__ float g_dinv[Nn];
__device__ int   g_off[Nn + 1];
__device__ int   g_fill[Nn];
__device__ int   g_csr_row[NEe];
__device__ float g_csr_norm[NEe];

// ---------------- HMMA primitive ----------------
__device__ __forceinline__ void hmma(float* d, uint32_t a0, uint32_t a1,
                                     uint32_t a2, uint32_t a3,
                                     uint32_t b0, uint32_t b1) {
    asm volatile(
        "mma.sync.aligned.m16n8k16.row.col.f32.bf16.bf16.f32 "
        "{%0,%1,%2,%3}, {%4,%5,%6,%7}, {%8,%9}, {%0,%1,%2,%3};\n"
        : "+f"(d[0]), "+f"(d[1]), "+f"(d[2]), "+f"(d[3])
        : "r"(a0), "r"(a1), "r"(a2), "r"(a3), "r"(b0), "r"(b1));
}

// ---------------- loop step GEMM: C[Nn x 384] = H @ Bpacked (bf16x3) ----------------
#define S_AHI 0
#define S_ALO 18432                 // 128*144
#define S_BHI 36864
#define S_BLO (36864 + 27648)       // 192*144
#define S_TOT (S_BLO + 27648)       // 92160

__global__ __launch_bounds__(512, 1) void mma_step(
    const __nv_bfloat16* __restrict__ Ahi, const __nv_bfloat16* __restrict__ Alo) {
    extern __shared__ char sm[];
    const int tid = threadIdx.x;
    const int brow = blockIdx.x * 128;
    const int bcol = blockIdx.y * 192;

#pragma unroll
    for (int i = 0; i < 2; i++) {
        int idx = tid * 2 + i;
        int r = idx >> 3, c = idx & 7;
        int gr = brow + r;
        uint4 vh = make_uint4(0, 0, 0, 0), vl = make_uint4(0, 0, 0, 0);
        if (gr < Nn) {
            vh = *reinterpret_cast<const uint4*>(&Ahi[(size_t)gr * HD + c * 8]);
            vl = *reinterpret_cast<const uint4*>(&Alo[(size_t)gr * HD + c * 8]);
        }
        *reinterpret_cast<uint4*>(sm + S_AHI + r * 144 + c * 16) = vh;
        *reinterpret_cast<uint4*>(sm + S_ALO + r * 144 + c * 16) = vl;
    }
#pragma unroll
    for (int i = 0; i < 3; i++) {
        int idx = tid * 3 + i;
        int r = idx >> 3, c = idx & 7;
        *reinterpret_cast<uint4*>(sm + S_BHI + r * 144 + c * 16) =
            *reinterpret_cast<const uint4*>(&g_Bhi[(size_t)(bcol + r) * HD + c * 8]);
        *reinterpret_cast<uint4*>(sm + S_BLO + r * 144 + c * 16) =
            *reinterpret_cast<const uint4*>(&g_Blo[(size_t)(bcol + r) * HD + c * 8]);
    }
    __syncthreads();

    const int wid = tid >> 5, lane = tid & 31;
    const int wm = wid >> 2, wn = wid & 3;
    const int g = lane >> 2, t = lane & 3;

    float acc[2][6][4];
#pragma unroll
    for (int mt = 0; mt < 2; mt++)
#pragma unroll
        for (int nt = 0; nt < 6; nt++)
#pragma unroll
            for (int q = 0; q < 4; q++) acc[mt][nt][q] = 0.f;

#pragma unroll
    for (int ab = 0; ab < 3; ab++) {
        const char* Ab = sm + ((ab == 2) ? S_ALO : S_AHI);
        const char* Bb = sm + ((ab == 1) ? S_BLO : S_BHI);
#pragma unroll
        for (int kc = 0; kc < 4; kc++) {
            int kb = kc * 32 + t * 4;
            uint32_t bf[6][2];
#pragma unroll
            for (int nt = 0; nt < 6; nt++) {
                int nr = wn * 48 + nt * 8 + g;
                bf[nt][0] = *reinterpret_cast<const uint32_t*>(Bb + nr * 144 + kb);
                bf[nt][1] = *reinterpret_cast<const uint32_t*>(Bb + nr * 144 + kb + 16);
            }
#pragma unroll
            for (int mt = 0; mt < 2; mt++) {
                int r0 = wm * 32 + mt * 16 + g;
                uint32_t a0 = *reinterpret_cast<const uint32_t*>(Ab + r0 * 144 + kb);
                uint32_t a1 = *reinterpret_cast<const uint32_t*>(Ab + (r0 + 8) * 144 + kb);
                uint32_t a2 = *reinterpret_cast<const uint32_t*>(Ab + r0 * 144 + kb + 16);
                uint32_t a3 = *reinterpret_cast<const uint32_t*>(Ab + (r0 + 8) * 144 + kb + 16);
#pragma unroll
                for (int nt = 0; nt < 6; nt++)
                    hmma(acc[mt][nt], a0, a1, a2, a3, bf[nt][0], bf[nt][1]);
            }
        }
    }

#pragma unroll
    for (int mt = 0; mt < 2; mt++) {
#pragma unroll
        for (int nt = 0; nt < 6; nt++) {
            int row = brow + wm * 32 + mt * 16 + g;
            int col = bcol + wn * 48 + nt * 8 + 2 * t;
            if (row < Nn) {
                float2 v = make_float2(acc[mt][nt][0], acc[mt][nt][1]);
                *reinterpret_cast<float2*>(&g_C[(size_t)row * NC + col]) = v;
            }
            if (row + 8 < Nn) {
                float2 v = make_float2(acc[mt][nt][2], acc[mt][nt][3]);
                *reinterpret_cast<float2*>(&g_C[(size_t)(row + 8) * NC + col]) = v;
            }
        }
    }
}

// ---------------- generic HMMA GEMM, N=64 ----------------
__global__ __launch_bounds__(512, 1) void mma_gemm64(
    const __nv_bfloat16* __restrict__ Ahi, const __nv_bfloat16* __restrict__ Alo,
    const __nv_bfloat16* __restrict__ Bhi, const __nv_bfloat16* __restrict__ Blo,
    float* __restrict__ C, int M, int K, int act) {
    extern __shared__ char sm[];
    const int tid = threadIdx.x;
    const int brow = blockIdx.x * 128;
    const int SB = K * 2 + 16;
    char* Ah = sm;
    char* Al = sm + 128 * SB;
    char* Bh = sm + 256 * SB;
    char* Bl = sm + 320 * SB;
    const int ku4 = K >> 3;

    for (int idx = tid; idx < 128 * ku4; idx += 512) {
        int r = idx / ku4, c = idx % ku4;
        int gr = brow + r;
        uint4 vh = make_uint4(0, 0, 0, 0), vl = make_uint4(0, 0, 0, 0);
        if (gr < M) {
            vh = *reinterpret_cast<const uint4*>(&Ahi[(size_t)gr * K + c * 8]);
            vl = *reinterpret_cast<const uint4*>(&Alo[(size_t)gr * K + c * 8]);
        }
        *reinterpret_cast<uint4*>(Ah + r * SB + c * 16) = vh;
        *reinterpret_cast<uint4*>(Al + r * SB + c * 16) = vl;
    }
    for (int idx = tid; idx < 64 * ku4; idx += 512) {
        int r = idx / ku4, c = idx % ku4;
        *reinterpret_cast<uint4*>(Bh + r * SB + c * 16) =
            *reinterpret_cast<const uint4*>(&Bhi[(size_t)r * K + c * 8]);
        *reinterpret_cast<uint4*>(Bl + r * SB + c * 16) =
            *reinterpret_cast<const uint4*>(&Blo[(size_t)r * K + c * 8]);
    }
    __syncthreads();

    const int wid = tid >> 5, lane = tid & 31;
    const int wm = wid >> 2, wn = wid & 3;
    const int g = lane >> 2, t = lane & 3;
    const int KC = K >> 4;

    float acc[2][2][4];
#pragma unroll
    for (int mt = 0; mt < 2; mt++)
#pragma unroll
        for (int nt = 0; nt < 2; nt++)
#pragma unroll
            for (int q = 0; q < 4; q++) acc[mt][nt][q] = 0.f;

#pragma unroll
    for (int ab = 0; ab < 3; ab++) {
        const char* A_ = (ab == 2) ? Al : Ah;
        const char* B_ = (ab == 1) ? Bl : Bh;
        for (int kc = 0; kc < KC; kc++) {
            int kb = kc * 32 + t * 4;
            uint32_t bf[2][2];
#pragma unroll
            for (int nt = 0; nt < 2; nt++) {
                int nr = wn * 16 + nt * 8 + g;
                bf[nt][0] = *reinterpret_cast<const uint32_t*>(B_ + nr * SB + kb);
                bf[nt][1] = *reinterpret_cast<const uint32_t*>(B_ + nr * SB + kb + 16);
            }
#pragma unroll
            for (int mt = 0; mt < 2; mt++) {
                int r0 = wm * 32 + mt * 16 + g;
                uint32_t a0 = *reinterpret_cast<const uint32_t*>(A_ + r0 * SB + kb);
                uint32_t a1 = *reinterpret_cast<const uint32_t*>(A_ + (r0 + 8) * SB + kb);
                uint32_t a2 = *reinterpret_cast<const uint32_t*>(A_ + r0 * SB + kb + 16);
                uint32_t a3 = *reinterpret_cast<const uint32_t*>(A_ + (r0 + 8) * SB + kb + 16);
#pragma unroll
                for (int nt = 0; nt < 2; nt++)
                    hmma(acc[mt][nt], a0, a1, a2, a3, bf[nt][0], bf[nt][1]);
            }
        }
    }

#pragma unroll
    for (int mt = 0; mt < 2; mt++) {
#pragma unroll
        for (int nt = 0; nt < 2; nt++) {
            int row = brow + wm * 32 + mt * 16 + g;
            int col = wn * 16 + nt * 8 + 2 * t;
            float v0 = acc[mt][nt][0], v1 = acc[mt][nt][1];
            float v2 = acc[mt][nt][2], v3 = acc[mt][nt][3];
            if (act) {
                v0 = fmaxf(v0, 0.f); v1 = fmaxf(v1, 0.f);
                v2 = fmaxf(v2, 0.f); v3 = fmaxf(v3, 0.f);
            }
            if (row < M)
                *reinterpret_cast<float2*>(&C[(size_t)row * 64 + col]) = make_float2(v0, v1);
            if (row + 8 < M)
                *reinterpret_cast<float2*>(&C[(size_t)(row + 8) * 64 + col]) = make_float2(v2, v3);
        }
    }
}

// ---------------- weight packing ----------------
__global__ void k_prepB(const float* __restrict__ Om, const float* __restrict__ Ws,
                        const float* __restrict__ Wfc1) {
    int i = blockIdx.x * blockDim.x + threadIdx.x;
    if (i >= HD * NC) return;
    int k = i / NC, j = i % NC;
    float v;
    if (j < 64)       v = Om[k * 64 + j] - Om[j * 64 + k];
    else if (j < 128) { int jj = j - 64; v = 0.5f * (Ws[k * 64 + jj] + Ws[jj * 64 + k]); }
    else if (j < 256) v = Wfc1[k * 128 + (j - 128)];
    else              v = Wfc1[(64 + k) * 128 + (j - 256)];
    __nv_bfloat16 hi = __float2bfloat16(v);
    __nv_bfloat16 lo = __float2bfloat16(v - __bfloat162float(hi));
    g_Bhi[(size_t)j * HD + k] = hi;
    g_Blo[(size_t)j * HD + k] = lo;
}

__global__ void k_prepW(const float* __restrict__ src, int K,
                        __nv_bfloat16* __restrict__ dhi, __nv_bfloat16* __restrict__ dlo) {
    int i = blockIdx.x * blockDim.x + threadIdx.x;
    if (i >= K * HD) return;
    int k = i / HD, n = i % HD;
    float v = src[i];
    __nv_bfloat16 hi = __float2bfloat16(v);
    dhi[(size_t)n * K + k] = hi;
    dlo[(size_t)n * K + k] = __float2bfloat16(v - __bfloat162float(hi));
}

// ---------------- graph preprocessing ----------------
__global__ void k_init() {
    int i = blockIdx.x * blockDim.x + threadIdx.x;
    if (i < Nn) { g_deg[i] = 1; g_fill[i] = 0; }
}

__global__ void k_deg(const int* __restrict__ ei) {
    int e = blockIdx.x * blockDim.x + threadIdx.x;
    if (e < Ee) atomicAdd(&g_deg[ei[Ee + e]], 1);
}

__global__ void k_dinv() {
    int n = blockIdx.x * blockDim.x + threadIdx.x;
    if (n < Nn) g_dinv[n] = rsqrtf((float)g_deg[n]);
}

__global__ void k_scan() {
    __shared__ int sh[1024];
    __shared__ int carry_s;
    int t = threadIdx.x;
    if (t == 0) carry_s = 0;
    __syncthreads();
    for (int base = 0; base < Nn; base += 1024) {
        int v = (base + t < Nn) ? g_deg[base + t] : 0;
        int x = v;
        for (int off = 1; off < 1024; off <<= 1) {
            sh[t] = x; __syncthreads();
            if (t >= off) x += sh[t - off];
            __syncthreads();
        }
        int carry = carry_s;
        if (base + t < Nn) g_off[base + t] = carry + x - v;
        __syncthreads();
        if (t == 1023) carry_s = carry + x;
        __syncthreads();
    }
    if (t == 0) g_off[Nn] = carry_s;
}

__global__ void k_fill(const int* __restrict__ ei) {
    int e = blockIdx.x * blockDim.x + threadIdx.x;
    if (e >= NEe) return;
    int r_, c_;
    if (e < Ee) { r_ = ei[e]; c_ = ei[Ee + e]; }
    else        { r_ = c_ = e - Ee; }
    int pos = g_off[c_] + atomicAdd(&g_fill[c_], 1);
    g_csr_row[pos]  = r_;
    g_csr_norm[pos] = g_dinv[r_] * g_dinv[c_];
}

// ---------------- input conversions ----------------
__global__ void k_x2b(const float* __restrict__ x) {
    int i = blockIdx.x * blockDim.x + threadIdx.x;
    if (i >= Nn * INF) return;
    float v = x[i];
    __nv_bfloat16 hi = __float2bfloat16(v);
    g_xhi[i] = hi;
    g_xlo[i] = __float2bfloat16(v - __bfloat162float(hi));
}

// H snapshot + bf16 split + a,b for step 0 (fused)
__global__ __launch_bounds__(256) void k_h2b_ab(const float* __restrict__ Wfv) {
    int warp = (blockIdx.x * blockDim.x + threadIdx.x) >> 5;
    int lane = threadIdx.x & 31;
    if (warp >= Nn) return;
    int n = warp;
    float h0 = g_H[n * HD + lane], h1 = g_H[n * HD + lane + 32];
    g_H0[n * HD + lane] = h0;
    g_H0[n * HD + lane + 32] = h1;
    __nv_bfloat16 hi0 = __float2bfloat16(h0);
    __nv_bfloat16 hi1 = __float2bfloat16(h1);
    g_Hhi[n * HD + lane]      = hi0;
    g_Hhi[n * HD + lane + 32] = hi1;
    g_Hlo[n * HD + lane]      = __float2bfloat16(h0 - __bfloat162float(hi0));
    g_Hlo[n * HD + lane + 32] = __float2bfloat16(h1 - __bfloat162float(hi1));
    float pa = h0 * Wfv[lane]      + h1 * Wfv[lane + 32];
    float pb = h0 * Wfv[64 + lane] + h1 * Wfv[96 + lane];
#pragma unroll
    for (int o = 16; o > 0; o >>= 1) {
        pa += __shfl_xor_sync(0xffffffffu, pa, o);
        pb += __shfl_xor_sync(0xffffffffu, pb, o);
    }
    if (lane == 0) { g_a[0][n] = pa; g_b[0][n] = pb; }
}

// ---------------- fused per-step kernel: node warps + pair warps ----------------
__global__ __launch_bounds__(256) void k_step(const int* __restrict__ pairs,
                                              const float* __restrict__ gum,
                                              const float* __restrict__ Wfc2,
                                              const float* __restrict__ Wfv,
                                              int l) {
    int warp = (blockIdx.x * blockDim.x + threadIdx.x) >> 5;
    int lane = threadIdx.x & 31;
    if (warp < Nn) {
        // ---- node path ----
        int n = warp;
        int beg = g_off[n], end = g_off[n + 1];
        float s0 = 0.f, s1 = 0.f;
        int i = beg;
        for (; i + 1 < end; i += 2) {
            int rs0 = __ldg(&g_csr_row[i]);
            int rs1 = __ldg(&g_csr_row[i + 1]);
            float w0 = __ldg(&g_csr_norm[i]);
            float w1 = __ldg(&g_csr_norm[i + 1]);
            const float* M0 = &g_C[(size_t)rs0 * NC + 64];
            const float* M1 = &g_C[(size_t)rs1 * NC + 64];
            float m00 = __ldg(&M0[lane]);
            float m01 = __ldg(&M0[lane + 32]);
            float m10 = __ldg(&M1[lane]);
            float m11 = __ldg(&M1[lane + 32]);
            s0 += m00 * w0 + m10 * w1;
            s1 += m01 * w0 + m11 * w1;
        }
        if (i < end) {
            int rs = __ldg(&g_csr_row[i]);
            float w = __ldg(&g_csr_norm[i]);
            const float* M0 = &g_C[(size_t)rs * NC + 64];
            s0 += __ldg(&M0[lane]) * w;
            s1 += __ldg(&M0[lane + 32]) * w;
        }
        float a0 = g_C[(size_t)n * NC + lane];
        float a1 = g_C[(size_t)n * NC + 32 + lane];
        float dh0 = fmaxf(tanhf(s0 - fmaxf(a0, 0.f)), 0.f);
        float dh1 = fmaxf(tanhf(s1 - fmaxf(a1, 0.f)), 0.f);
        __nv_bfloat16* slab = &g_dHall[(size_t)l * Nn * HD];
        slab[n * HD + lane]      = __float2bfloat16(dh0);
        slab[n * HD + lane + 32] = __float2bfloat16(dh1);
        // H update in place + bf16 hi/lo emit
        float hn0 = g_H[n * HD + lane] + dh0;
        float hn1 = g_H[n * HD + lane + 32] + dh1;
        g_H[n * HD + lane]      = hn0;
        g_H[n * HD + lane + 32] = hn1;
        __nv_bfloat16 hi0 = __float2bfloat16(hn0);
        __nv_bfloat16 hi1 = __float2bfloat16(hn1);
        g_Hhi[n * HD + lane]      = hi0;
        g_Hhi[n * HD + lane + 32] = hi1;
        g_Hlo[n * HD + lane]      = __float2bfloat16(hn0 - __bfloat162float(hi0));
        g_Hlo[n * HD + lane + 32] = __float2bfloat16(hn1 - __bfloat162float(hi1));
        // nu partials for NEXT step (from updated H)
        float pa = hn0 * Wfv[lane]      + hn1 * Wfv[lane + 32];
        float pb = hn0 * Wfv[64 + lane] + hn1 * Wfv[96 + lane];
#pragma unroll
        for (int o = 16; o > 0; o >>= 1) {
            pa += __shfl_xor_sync(0xffffffffu, pa, o);
            pb += __shfl_xor_sync(0xffffffffu, pb, o);
        }
        if (lane == 0) { g_a[(l + 1) & 1][n] = pa; g_b[(l + 1) & 1][n] = pb; }
    } else {
        // ---- pair path ----
        int p = warp - Nn;
        if (p >= Pp) return;
        int s = pairs[2 * p], d = pairs[2 * p + 1];
        const float* Us = &g_C[(size_t)s * NC + 128];
        const float* Vd = &g_C[(size_t)d * NC + 256];
        float l0 = 0.f, l1 = 0.f;
#pragma unroll
        for (int i = 0; i < 4; i++) {
            int j = lane + 32 * i;
            float hv = fmaxf(__ldg(&Us[j]) + __ldg(&Vd[j]), 0.f);
            l0 += hv * Wfc2[2 * j];
            l1 += hv * Wfc2[2 * j + 1];
        }
#pragma unroll
        for (int o = 16; o > 0; o >>= 1) {
            l0 += __shfl_xor_sync(0xffffffffu, l0, o);
            l1 += __shfl_xor_sync(0xffffffffu, l1, o);
        }
        if (lane == 0) {
            float z  = g_a[l & 1][s] + g_b[l & 1][d];
            float nu = fmaxf(z, 0.f) + log1pf(expf(-fabsf(z))) + 1.0f;
            float g0 = __ldg(&gum[((size_t)l * Pp + p) * 2]);
            float g1 = __ldg(&gum[((size_t)l * Pp + p) * 2 + 1]);
            float diff = ((l1 + g1) - (l0 + g0)) / nu;
            g_tau[(size_t)l * Pp + p] = 1.f / (1.f + expf(diff));
        }
    }
}

// ---------------- final: assemble r in registers -> bf16 hi/lo, write ts ----------------
// lane handles logical cols (2*lane, 2*lane+1) of each 64-wide half.
__global__ __launch_bounds__(256) void k_final(const int* __restrict__ pairs,
                                               float* __restrict__ out) {
    int warp = (blockIdx.x * blockDim.x + threadIdx.x) >> 5;
    int lane = threadIdx.x & 31;
    if (warp >= Pp) return;
    int p = warp;
    int s = pairs[2 * p], d = pairs[2 * p + 1];
    float2 hs = *reinterpret_cast<const float2*>(&g_H0[s * HD + 2 * lane]);
    float2 hd = *reinterpret_cast<const float2*>(&g_H0[d * HD + 2 * lane]);
    float r0 = hs.x, r1 = hs.y;     // s-half cols 2l, 2l+1
    float r2 = hd.x, r3 = hd.y;     // d-half cols 2l, 2l+1
    float tval = (lane < Ll) ? g_tau[(size_t)lane * Pp + p] : 0.f;
    float ts = 0.f;
#pragma unroll
    for (int l = 0; l < Ll; l++) {
        float tau = __shfl_sync(0xffffffffu, tval, l);
        const __nv_bfloat16* slab = &g_dHall[(size_t)l * Nn * HD];
        __nv_bfloat162 ds = *reinterpret_cast<const __nv_bfloat162*>(&slab[s * HD + 2 * lane]);
        __nv_bfloat162 dd = *reinterpret_cast<const __nv_bfloat162*>(&slab[d * HD + 2 * lane]);
        r0 += tau * __bfloat162float(ds.x);
        r1 += tau * __bfloat162float(ds.y);
        r2 += tau * __bfloat162float(dd.x);
        r3 += tau * __bfloat162float(dd.y);
        ts += tau;
    }
    size_t base = (size_t)p * 2 * HD;
    __nv_bfloat16 h0 = __float2bfloat16(r0);
    __nv_bfloat16 h1 = __float2bfloat16(r1);
    __nv_bfloat16 h2 = __float2bfloat16(r2);
    __nv_bfloat16 h3 = __float2bfloat16(r3);
    __nv_bfloat162 lo01, lo23;
    lo01.x = __float2bfloat16(r0 - __bfloat162float(h0));
    lo01.y = __float2bfloat16(r1 - __bfloat162float(h1));
    lo23.x = __float2bfloat16(r2 - __bfloat162float(h2));
    lo23.y = __float2bfloat16(r3 - __bfloat162float(h3));
    __nv_bfloat162 hi01; hi01.x = h0; hi01.y = h1;
    __nv_bfloat162 hi23; hi23.x = h2; hi23.y = h3;
    *reinterpret_cast<__nv_bfloat162*>(&g_rhi[base + 2 * lane]) = hi01;
    *reinterpret_cast<__nv_bfloat162*>(&g_rhi[base + HD + 2 * lane]) = hi23;
    *reinterpret_cast<__nv_bfloat162*>(&g_rlo[base + 2 * lane]) = lo01;
    *reinterpret_cast<__nv_bfloat162*>(&g_rlo[base + HD + 2 * lane]) = lo23;
    if (lane == 0) out[Pp + p] = ts;
}

// ---------------- final scores ----------------
__global__ __launch_bounds__(256) void k_score(const float* __restrict__ Wp2,
                                               float* __restrict__ out) {
    int warp = (blockIdx.x * blockDim.x + threadIdx.x) >> 5;
    int lane = threadIdx.x & 31;
    if (warp >= Pp) return;
    int p = warp;
    float t0 = g_C[(size_t)p * 64 + 2 * lane];
    float t1 = g_C[(size_t)p * 64 + 2 * lane + 1];
    float acc = t0 * Wp2[2 * lane] + t1 * Wp2[2 * lane + 1];
#pragma unroll
    for (int o = 16; o > 0; o >>= 1) acc += __shfl_xor_sync(0xffffffffu, acc, o);
    if (lane == 0) out[p] = acc;
}

// ---------------- host ----------------
extern "C" void kernel_launch(void* const* d_in, const int* in_sizes, int n_in,
                              void* d_out, int out_size) {
    const float* x    = (const float*)d_in[0];
    const int*   ei   = (const int*)d_in[1];
    const int*   pairs= (const int*)d_in[2];
    const float* gum  = (const float*)d_in[3];
    const float* Wenc = (const float*)d_in[4];
    const float* Om   = (const float*)d_in[5];
    const float* Wsr  = (const float*)d_in[6];
    const float* Wfc1 = (const float*)d_in[7];
    const float* Wfc2 = (const float*)d_in[8];
    const float* Wfv  = (const float*)d_in[9];
    const float* Wp1  = (const float*)d_in[10];
    const float* Wp2  = (const float*)d_in[11];
    float* out = (float*)d_out;

    void *pH, *pC, *pHhi, *pHlo, *pXhi, *pXlo, *pWeh, *pWel, *pWph, *pWpl, *pRhi, *pRlo;
    cudaGetSymbolAddress(&pH, g_H);
    cudaGetSymbolAddress(&pC, g_C);
    cudaGetSymbolAddress(&pHhi, g_Hhi);
    cudaGetSymbolAddress(&pHlo, g_Hlo);
    cudaGetSymbolAddress(&pXhi, g_xhi);
    cudaGetSymbolAddress(&pXlo, g_xlo);
    cudaGetSymbolAddress(&pWeh, g_Wehi);
    cudaGetSymbolAddress(&pWel, g_Welo);
    cudaGetSymbolAddress(&pWph, g_Wp1hi);
    cudaGetSymbolAddress(&pWpl, g_Wp1lo);
    cudaGetSymbolAddress(&pRhi, g_rhi);
    cudaGetSymbolAddress(&pRlo, g_rlo);
    float* H_ = (float*)pH;
    float* C_ = (float*)pC;
    const __nv_bfloat16* Hhi_ = (const __nv_bfloat16*)pHhi;
    const __nv_bfloat16* Hlo_ = (const __nv_bfloat16*)pHlo;

    cudaFuncSetAttribute(mma_step, cudaFuncAttributeMaxDynamicSharedMemorySize, S_TOT);
    const int SM64 = 384 * (INF * 2 + 16);   // 104448 for K=128
    cudaFuncSetAttribute(mma_gemm64, cudaFuncAttributeMaxDynamicSharedMemorySize, SM64);

    // weights + graph prep + input conversion
    k_prepB<<<(HD * NC + 255) / 256, 256>>>(Om, Wsr, Wfc1);
    k_prepW<<<(INF * HD + 255) / 256, 256>>>(Wenc, INF, (__nv_bfloat16*)pWeh, (__nv_bfloat16*)pWel);
    k_prepW<<<(INF * HD + 255) / 256, 256>>>(Wp1, INF, (__nv_bfloat16*)pWph, (__nv_bfloat16*)pWpl);
    k_x2b<<<(Nn * INF + 255) / 256, 256>>>(x);
    k_init<<<(Nn + 255) / 256, 256>>>();
    k_deg<<<(Ee + 255) / 256, 256>>>(ei);
    k_dinv<<<(Nn + 255) / 256, 256>>>();
    k_scan<<<1, 1024>>>();
    k_fill<<<(NEe + 255) / 256, 256>>>(ei);

    // H0 = relu(x @ Wenc) via HMMA; fused snapshot/split/ab
    mma_gemm64<<<(Nn + 127) / 128, 512, SM64>>>(
        (const __nv_bfloat16*)pXhi, (const __nv_bfloat16*)pXlo,
        (const __nv_bfloat16*)pWeh, (const __nv_bfloat16*)pWel, H_, Nn, INF, 1);
    k_h2b_ab<<<(Nn * 32 + 255) / 256, 256>>>(Wfv);

    dim3 grid_mma((Nn + 127) / 128, 2);
    int step_blocks = ((Nn + Pp) * 32 + 255) / 256;
    for (int l = 0; l < Ll; l++) {
        mma_step<<<grid_mma, 512, S_TOT>>>(Hhi_, Hlo_);
        k_step<<<step_blocks, 256>>>(pairs, gum, Wfc2, Wfv, l);
    }

    // r (bf16 hi/lo) + ts, then T = relu(r @ Wp1) via HMMA, then scores
    k_final<<<(Pp * 32 + 255) / 256, 256>>>(pairs, out);
    mma_gemm64<<<(Pp + 127) / 128, 512, SM64>>>(
        (const __nv_bfloat16*)pRhi, (const __nv_bfloat16*)pRlo,
        (const __nv_bfloat16*)pWph, (const __nv_bfloat16*)pWpl, C_, Pp, INF, 1);
    k_score<<<(Pp * 32 + 255) / 256, 256>>>(Wp2, out);
}